// round 1
// baseline (speedup 1.0000x reference)
#include <cuda_runtime.h>
#include <cstdint>
#include <cstddef>

// ---------------- problem constants ----------------
#define SS      4096        // sequence length
#define EMB     2048
#define PROJD   10304       // INTER + CONV_D + NH
#define INTERD  4096        // H*P
#define CONVD   6144        // INTER + 2*G*N
#define NH      64          // heads
#define HP      64          // head dim P
#define SN      128         // state dim N
#define NG      8           // groups
#define CSZ     256         // chunk size
#define NCH     16          // num chunks
#define DTOFF   10240       // INTER + CONV_D

// ---------------- scratch (device globals; no allocs allowed) ----------------
__device__ float g_proj[(size_t)SS * PROJD];    // 168.8 MB
__device__ float g_hconv[(size_t)SS * CONVD];   // 100.7 MB
__device__ float g_dt2[SS * NH];
__device__ float g_acum[NH * SS];               // [h][t], per-chunk inclusive cumsum
__device__ float g_y[(size_t)SS * INTERD];
__device__ float g_norm[(size_t)SS * INTERD];

// ---------------- SGEMM: C[M,N] = A[M,K] * B[N,K]^T (both row-major, K-contig) ----------------
__global__ __launch_bounds__(256, 2)
void sgemm_nt(const float* __restrict__ A, const float* __restrict__ B,
              float* __restrict__ C, int M, int N, int K) {
    __shared__ float As[8][128];
    __shared__ float Bs[8][128];
    const int tid = threadIdx.x;
    const int m0 = blockIdx.y * 128;
    const int n0 = blockIdx.x * 128;
    const int tx = tid & 15, ty = tid >> 4;
    const int lrow = tid >> 1;
    const int lcol = (tid & 1) << 2;

    float acc[8][8];
#pragma unroll
    for (int i = 0; i < 8; i++)
#pragma unroll
        for (int j = 0; j < 8; j++) acc[i][j] = 0.f;

    const float* Ap = A + (size_t)(m0 + lrow) * K + lcol;
    const float* Bp = B + (size_t)(n0 + lrow) * K + lcol;
    const bool bvalid = (n0 + lrow) < N;

    for (int k0 = 0; k0 < K; k0 += 8) {
        float4 av = *(const float4*)(Ap + k0);
        float4 bv = make_float4(0.f, 0.f, 0.f, 0.f);
        if (bvalid) bv = *(const float4*)(Bp + k0);
        As[lcol + 0][lrow] = av.x; As[lcol + 1][lrow] = av.y;
        As[lcol + 2][lrow] = av.z; As[lcol + 3][lrow] = av.w;
        Bs[lcol + 0][lrow] = bv.x; Bs[lcol + 1][lrow] = bv.y;
        Bs[lcol + 2][lrow] = bv.z; Bs[lcol + 3][lrow] = bv.w;
        __syncthreads();
#pragma unroll
        for (int kk = 0; kk < 8; kk++) {
            float a[8], b[8];
            *(float4*)(a)     = *(const float4*)&As[kk][ty * 8];
            *(float4*)(a + 4) = *(const float4*)&As[kk][ty * 8 + 4];
            *(float4*)(b)     = *(const float4*)&Bs[kk][tx * 8];
            *(float4*)(b + 4) = *(const float4*)&Bs[kk][tx * 8 + 4];
#pragma unroll
            for (int i = 0; i < 8; i++)
#pragma unroll
                for (int j = 0; j < 8; j++) acc[i][j] += a[i] * b[j];
        }
        __syncthreads();
    }

#pragma unroll
    for (int i = 0; i < 8; i++) {
        const int m = m0 + ty * 8 + i;
        float* Cr = C + (size_t)m * N + n0 + tx * 8;
        if (n0 + 128 <= N) {
            *(float4*)(Cr)     = make_float4(acc[i][0], acc[i][1], acc[i][2], acc[i][3]);
            *(float4*)(Cr + 4) = make_float4(acc[i][4], acc[i][5], acc[i][6], acc[i][7]);
        } else {
#pragma unroll
            for (int j = 0; j < 8; j++)
                if (n0 + tx * 8 + j < N) Cr[j] = acc[i][j];
        }
    }
}

// ---------------- depthwise causal conv (K=4) + bias + silu ----------------
__global__ void conv_silu_kernel(const float* __restrict__ cw, const float* __restrict__ cb) {
    const int c = blockIdx.x * 256 + threadIdx.x;   // 0..6143
    const int t = blockIdx.y;                       // 0..4095
    float acc = cb[c];
#pragma unroll
    for (int k = 0; k < 4; k++) {
        const int tt = t - 3 + k;
        if (tt >= 0) acc += g_proj[(size_t)tt * PROJD + INTERD + c] * cw[c * 4 + k];
    }
    g_hconv[(size_t)t * CONVD + c] = acc / (1.f + __expf(-acc));
}

// ---------------- dt2 = softplus(dt + dt_bias) ----------------
__global__ void dt2_kernel(const float* __restrict__ dt_bias) {
    const int idx = blockIdx.x * 256 + threadIdx.x;   // 0..262143
    const int t = idx >> 6;
    const int h = idx & 63;
    const float x = g_proj[(size_t)t * PROJD + DTOFF + h] + dt_bias[h];
    g_dt2[idx] = (x > 20.f) ? x : log1pf(expf(x));
}

// ---------------- per-(head,chunk) inclusive cumsum of A*dt2 ----------------
__global__ void acum_kernel(const float* __restrict__ A_log) {
    const int chunk = blockIdx.x;
    const int h = blockIdx.y;
    const int tid = threadIdx.x;
    const float Ah = -expf(A_log[h]);
    __shared__ float s[CSZ];
    const int t = chunk * CSZ + tid;
    s[tid] = Ah * g_dt2[t * NH + h];
    for (int off = 1; off < CSZ; off <<= 1) {
        __syncthreads();
        const float v = (tid >= off) ? s[tid - off] : 0.f;
        __syncthreads();
        s[tid] += v;
    }
    g_acum[h * SS + t] = s[tid];
}

// ---------------- fused SSD per (chunk, head) ----------------
// Y[i,p] = sum_j (C_i . B_j) * w(i,j) * (hid_j * dt2_j)[p] + D[h]*hid_i[p]
// w(i,j) = [j<=i] exp(a_i - a_j) + exp(a_i - a_j + a_last)   (exponents all <= 0)
#define SSD_SMEM_FLOATS (8320 + 4096 + 4112 + 16640 + 256)
__global__ __launch_bounds__(256, 1)
void ssd_kernel(const float* __restrict__ Dp) {
    extern __shared__ float sm[];
    float* Bts = sm;                         // [128][65]  B^T tile
    float* Xt  = sm + 8320;                  // [64][64]   hid*dt2 tile
    float* Cs  = sm + 8320 + 4096;           // [16][257]  C n-slab (transposed)
    float* Gw  = sm + 8320 + 4096 + 4112;    // [256][65]  weighted Gram tile
    float* acs = Gw + 16640;                 // [256]

    const int tid = threadIdx.x;
    const int chunk = blockIdx.x;
    const int h = blockIdx.y;
    const int t0 = chunk * CSZ;
    const int grp = h & 7;
    const int Bbase = INTERD + grp * SN;
    const int Cbase = INTERD + NG * SN + grp * SN;
    const int tx = tid & 15, ty = tid >> 4;

    acs[tid] = g_acum[h * SS + t0 + tid];
    __syncthreads();
    const float alast = acs[CSZ - 1];

    float yacc[64];
#pragma unroll
    for (int p = 0; p < 64; p++) yacc[p] = 0.f;

    for (int jt = 0; jt < 4; ++jt) {
        const int jbase = jt * 64;
        // load B tile transposed: Bts[n][j']
#pragma unroll
        for (int it = 0; it < 8; ++it) {
            const int idx = it * 256 + tid;
            const int jj = idx >> 5;
            const int n4 = (idx & 31) << 2;
            const float4 v = *(const float4*)(g_hconv + (size_t)(t0 + jbase + jj) * CONVD + Bbase + n4);
            Bts[(n4 + 0) * 65 + jj] = v.x; Bts[(n4 + 1) * 65 + jj] = v.y;
            Bts[(n4 + 2) * 65 + jj] = v.z; Bts[(n4 + 3) * 65 + jj] = v.w;
        }
        // load Xt = hid * dt2
#pragma unroll
        for (int it = 0; it < 4; ++it) {
            const int idx = it * 256 + tid;
            const int jj = idx >> 4;
            const int p4 = (idx & 15) << 2;
            const int tj = t0 + jbase + jj;
            float4 v = *(const float4*)(g_hconv + (size_t)tj * CONVD + h * HP + p4);
            const float sc = g_dt2[tj * NH + h];
            v.x *= sc; v.y *= sc; v.z *= sc; v.w *= sc;
            *(float4*)(Xt + jj * 64 + p4) = v;
        }
        __syncthreads();

        // stage 1: Gm[i,j'] = C_i . B_j'  (contract n in slabs of 16)
        float gacc[64];
#pragma unroll
        for (int q = 0; q < 64; q++) gacc[q] = 0.f;
        for (int n0 = 0; n0 < SN; n0 += 16) {
#pragma unroll
            for (int it = 0; it < 16; ++it) {
                const int idx = it * 256 + tid;
                const int i = idx >> 4;
                const int nn = idx & 15;
                Cs[nn * 257 + i] = g_hconv[(size_t)(t0 + i) * CONVD + Cbase + n0 + nn];
            }
            __syncthreads();
#pragma unroll
            for (int kk = 0; kk < 16; kk++) {
                float a[16];
#pragma unroll
                for (int u = 0; u < 16; u++) a[u] = Cs[kk * 257 + ty * 16 + u];
                const float* br = Bts + (n0 + kk) * 65 + tx * 4;
                const float b0 = br[0], b1 = br[1], b2 = br[2], b3 = br[3];
#pragma unroll
                for (int u = 0; u < 16; u++) {
                    gacc[u * 4 + 0] += a[u] * b0;
                    gacc[u * 4 + 1] += a[u] * b1;
                    gacc[u * 4 + 2] += a[u] * b2;
                    gacc[u * 4 + 3] += a[u] * b3;
                }
            }
            __syncthreads();
        }
        // apply decay weights, write Gw
#pragma unroll
        for (int u = 0; u < 16; u++) {
            const int i = ty * 16 + u;
            const float ai = acs[i];
#pragma unroll
            for (int v = 0; v < 4; v++) {
                const int j = tx * 4 + v;
                const int jg = jbase + j;
                const float d = ai - acs[jg];
                float w = __expf(d + alast);
                if (jg <= i) w += __expf(d);
                Gw[i * 65 + j] = gacc[u * 4 + v] * w;
            }
        }
        __syncthreads();
        // stage 2: Y[i] += Gw[i,:] @ Xt
#pragma unroll 4
        for (int j = 0; j < 64; j++) {
            const float gv = Gw[tid * 65 + j];
            const float4* xr = (const float4*)(Xt + (j << 6));
#pragma unroll
            for (int p4 = 0; p4 < 16; p4++) {
                const float4 xv = xr[p4];
                yacc[p4 * 4 + 0] += gv * xv.x;
                yacc[p4 * 4 + 1] += gv * xv.y;
                yacc[p4 * 4 + 2] += gv * xv.z;
                yacc[p4 * 4 + 3] += gv * xv.w;
            }
        }
        __syncthreads();
    }

    // D residual
    const float Dh = Dp[h];
    const float4* hrow = (const float4*)(g_hconv + (size_t)(t0 + tid) * CONVD + h * HP);
#pragma unroll
    for (int p4 = 0; p4 < 16; p4++) {
        const float4 hv = hrow[p4];
        yacc[p4 * 4 + 0] += Dh * hv.x;
        yacc[p4 * 4 + 1] += Dh * hv.y;
        yacc[p4 * 4 + 2] += Dh * hv.z;
        yacc[p4 * 4 + 3] += Dh * hv.w;
    }
    // stage through smem for coalesced store
#pragma unroll
    for (int p = 0; p < 64; p++) Gw[tid * 65 + p] = yacc[p];
    __syncthreads();
#pragma unroll
    for (int it = 0; it < 16; ++it) {
        const int idx = it * 256 + tid;
        const int i = idx >> 4;
        const int p4 = (idx & 15) << 2;
        float4 v;
        v.x = Gw[i * 65 + p4 + 0]; v.y = Gw[i * 65 + p4 + 1];
        v.z = Gw[i * 65 + p4 + 2]; v.w = Gw[i * 65 + p4 + 3];
        *(float4*)(g_y + (size_t)(t0 + i) * INTERD + h * HP + p4) = v;
    }
}

// ---------------- gate silu + RMSNorm ----------------
__global__ void norm_kernel(const float* __restrict__ norm_w) {
    const int t = blockIdx.x;
    const int tid = threadIdx.x;
    __shared__ float red[256];
    float local = 0.f;
    for (int c = tid; c < INTERD; c += 256) {
        const float g = g_proj[(size_t)t * PROJD + c];
        const float yv = g_y[(size_t)t * INTERD + c];
        const float yg = yv * (g / (1.f + __expf(-g)));
        g_y[(size_t)t * INTERD + c] = yg;
        local += yg * yg;
    }
    red[tid] = local;
    __syncthreads();
    for (int s = 128; s > 0; s >>= 1) {
        if (tid < s) red[tid] += red[tid + s];
        __syncthreads();
    }
    const float rstd = rsqrtf(red[0] / (float)INTERD + 1e-6f);
    for (int c = tid; c < INTERD; c += 256) {
        g_norm[(size_t)t * INTERD + c] = norm_w[c] * g_y[(size_t)t * INTERD + c] * rstd;
    }
}

// ---------------- launch ----------------
extern "C" void kernel_launch(void* const* d_in, const int* in_sizes, int n_in,
                              void* d_out, int out_size) {
    (void)in_sizes; (void)n_in; (void)out_size;
    const float* x       = (const float*)d_in[0];
    const float* w_in    = (const float*)d_in[1];
    const float* conv_w  = (const float*)d_in[2];
    const float* conv_b  = (const float*)d_in[3];
    const float* dt_bias = (const float*)d_in[4];
    const float* A_log   = (const float*)d_in[5];
    const float* Dv      = (const float*)d_in[6];
    const float* norm_w  = (const float*)d_in[7];
    const float* w_out   = (const float*)d_in[8];
    float* out = (float*)d_out;

    float* p_proj = nullptr;
    float* p_norm = nullptr;
    cudaGetSymbolAddress((void**)&p_proj, g_proj);
    cudaGetSymbolAddress((void**)&p_norm, g_norm);

    // 1) proj = X @ W_in^T   [4096 x 10304]
    sgemm_nt<<<dim3((PROJD + 127) / 128, SS / 128), 256>>>(x, w_in, p_proj, SS, PROJD, EMB);
    // 2) depthwise causal conv + silu
    conv_silu_kernel<<<dim3(CONVD / 256, SS), 256>>>(conv_w, conv_b);
    // 3) dt2 = softplus(dt + bias)
    dt2_kernel<<<(SS * NH) / 256, 256>>>(dt_bias);
    // 4) per-chunk cumsum of A*dt2
    acum_kernel<<<dim3(NCH, NH), 256>>>(A_log);
    // 5) fused SSD
    const int ssd_smem = SSD_SMEM_FLOATS * (int)sizeof(float);
    cudaFuncSetAttribute(ssd_kernel, cudaFuncAttributeMaxDynamicSharedMemorySize, ssd_smem);
    ssd_kernel<<<dim3(NCH, NH), 256, ssd_smem>>>(Dv);
    // 6) gate + rmsnorm
    norm_kernel<<<SS, 256>>>(norm_w);
    // 7) out = normed @ W_out^T   [4096 x 2048]
    sgemm_nt<<<dim3(EMB / 128, SS / 128), 256>>>(p_norm, w_out, out, SS, EMB, INTERD);
}

// round 3
// speedup vs baseline: 3.7034x; 3.7034x over previous
#include <cuda_runtime.h>
#include <cuda_bf16.h>
#include <cstdint>
#include <cstddef>

// ---------------- problem constants ----------------
#define SS      4096        // sequence length
#define EMB     2048
#define PROJD   10304       // INTER + CONV_D + NH
#define PROJPAD 10368       // padded to 128*81
#define INTERD  4096        // H*P
#define CONVD   6144        // INTER + 2*G*N
#define NH      64          // heads
#define HP      64          // head dim P
#define SN      128         // state dim N
#define NG      8           // groups
#define CSZ     256         // chunk size
#define NCH     16          // num chunks
#define DTOFF   10240       // INTER + CONV_D

// ---------------- scratch (device globals; no allocs allowed) ----------------
__device__ float g_proj[(size_t)SS * PROJD];
__device__ float g_hconv[(size_t)SS * CONVD];
__device__ float g_dt2[SS * NH];
__device__ float g_acum[NH * SS];
__device__ float g_y[(size_t)SS * INTERD];
__device__ float g_norm[(size_t)SS * INTERD];
// bf16-split packed operands (K tripled)
__device__ __nv_bfloat16 g_Apack[(size_t)SS * 3 * INTERD];
__device__ __nv_bfloat16 g_B1[(size_t)PROJPAD * 3 * EMB];
__device__ __nv_bfloat16 g_B2[(size_t)EMB * 3 * INTERD];

// ================= helpers =================
__device__ __forceinline__ uint32_t smem_u32(const void* p) {
    uint32_t a;
    asm("{ .reg .u64 t; cvta.to.shared.u64 t, %1; cvt.u32.u64 %0, t; }" : "=r"(a) : "l"(p));
    return a;
}
__device__ __forceinline__ void cp_async16(uint32_t saddr, const void* g) {
    asm volatile("cp.async.cg.shared.global [%0], [%1], 16;" :: "r"(saddr), "l"(g) : "memory");
}
#define CP_COMMIT() asm volatile("cp.async.commit_group;" ::: "memory")

__device__ __forceinline__ void ldsm_x4(uint32_t addr, uint32_t& r0, uint32_t& r1,
                                        uint32_t& r2, uint32_t& r3) {
    asm volatile("ldmatrix.sync.aligned.m8n8.x4.shared.b16 {%0,%1,%2,%3}, [%4];"
                 : "=r"(r0), "=r"(r1), "=r"(r2), "=r"(r3) : "r"(addr));
}
__device__ __forceinline__ void mma_bf16(float* d, const uint32_t* a, uint32_t b0, uint32_t b1) {
    asm volatile(
        "mma.sync.aligned.m16n8k16.row.col.f32.bf16.bf16.f32 "
        "{%0,%1,%2,%3}, {%4,%5,%6,%7}, {%8,%9}, {%0,%1,%2,%3};"
        : "+f"(d[0]), "+f"(d[1]), "+f"(d[2]), "+f"(d[3])
        : "r"(a[0]), "r"(a[1]), "r"(a[2]), "r"(a[3]), "r"(b0), "r"(b1));
}

// ================= split-pack (vectorized) =================
// mode 0 (A): [hi | lo | hi]; mode 1 (B): [hi | hi | lo]; rows >= srcRows -> zeros
__global__ void pack_split(const float* __restrict__ src, __nv_bfloat16* __restrict__ dst,
                           int srcRows, int dstRows, int K, int mode) {
    const int K8 = K >> 3;
    const size_t total = (size_t)dstRows * K8;
    for (size_t v = (size_t)blockIdx.x * 256 + threadIdx.x; v < total;
         v += (size_t)gridDim.x * 256) {
        const int r = (int)(v / K8);
        const int k = (int)(v - (size_t)r * K8) << 3;
        float x[8];
        if (r < srcRows) {
            const float4 f0 = *(const float4*)(src + (size_t)r * K + k);
            const float4 f1 = *(const float4*)(src + (size_t)r * K + k + 4);
            x[0] = f0.x; x[1] = f0.y; x[2] = f0.z; x[3] = f0.w;
            x[4] = f1.x; x[5] = f1.y; x[6] = f1.z; x[7] = f1.w;
        } else {
#pragma unroll
            for (int i = 0; i < 8; i++) x[i] = 0.f;
        }
        union { __nv_bfloat16 h[8]; uint4 u; } uh, ul;
#pragma unroll
        for (int i = 0; i < 8; i++) {
            uh.h[i] = __float2bfloat16(x[i]);
            ul.h[i] = __float2bfloat16(x[i] - __bfloat162float(uh.h[i]));
        }
        const size_t ro = (size_t)r * 3 * K + k;
        *(uint4*)(dst + ro) = uh.u;
        if (mode == 0) {
            *(uint4*)(dst + ro + K) = ul.u;
            *(uint4*)(dst + ro + 2 * K) = uh.u;
        } else {
            *(uint4*)(dst + ro + K) = uh.u;
            *(uint4*)(dst + ro + 2 * K) = ul.u;
        }
    }
}

// ================= HMMA GEMM: C[M,N] = A[M,K3] * B[N,K3]^T =================
// bf16 inputs, fp32 accumulate. CTA 128x128, BK=32, 4-stage cp.async pipeline.
#define GSTAGES 4
#define GSTAGE_BYTES 16384           // A 8KB + B 8KB
#define GEMM_DYN_SMEM (GSTAGES * GSTAGE_BYTES)

__device__ __forceinline__ void gemm_load_stage(
    const __nv_bfloat16* __restrict__ A, const __nv_bfloat16* __restrict__ B,
    int K3, int m0, int n0, int tid, uint32_t sb, int stage, int kk) {
    const uint32_t abase = sb + stage * GSTAGE_BYTES;
    const uint32_t bbase = abase + 8192;
    const int k0 = kk * 32;
#pragma unroll
    for (int it = 0; it < 2; it++) {
        const int idx = it * 256 + tid;          // 0..511
        const int row = idx >> 2;
        const int ch = idx & 3;
        const int csw = ch ^ ((row >> 1) & 3);
        cp_async16(abase + row * 64 + csw * 16,
                   A + (size_t)(m0 + row) * K3 + k0 + ch * 8);
    }
#pragma unroll
    for (int it = 0; it < 2; it++) {
        const int idx = it * 256 + tid;
        const int row = idx >> 2;
        const int ch = idx & 3;
        const int csw = ch ^ ((row >> 1) & 3);
        cp_async16(bbase + row * 64 + csw * 16,
                   B + (size_t)(n0 + row) * K3 + k0 + ch * 8);
    }
}

__global__ __launch_bounds__(256)
void tgemm(const __nv_bfloat16* __restrict__ A, const __nv_bfloat16* __restrict__ B,
           float* __restrict__ C, int K3, int Nvalid, int Nstride) {
    extern __shared__ char dynsm[];
    const uint32_t sb = smem_u32(dynsm);
    const int tid = threadIdx.x;
    const int lane = tid & 31;
    const int wid = tid >> 5;
    const int wm = wid & 3;          // 4 warps along M (32 rows each)
    const int wn = wid >> 2;         // 2 warps along N (64 cols each)
    const int m0 = blockIdx.x * 128;
    const int n0 = blockIdx.y * 128;
    const int nK = K3 >> 5;

    float acc[2][8][4];
#pragma unroll
    for (int i = 0; i < 2; i++)
#pragma unroll
        for (int j = 0; j < 8; j++)
#pragma unroll
            for (int q = 0; q < 4; q++) acc[i][j][q] = 0.f;

    // prologue: stages 0..2
    gemm_load_stage(A, B, K3, m0, n0, tid, sb, 0, 0); CP_COMMIT();
    gemm_load_stage(A, B, K3, m0, n0, tid, sb, 1, 1); CP_COMMIT();
    gemm_load_stage(A, B, K3, m0, n0, tid, sb, 2, 2); CP_COMMIT();

    // precomputed ldmatrix lane addressing (row, chunk-group), swizzle applied inline
    const int a_row = wm * 32 + (lane & 15);        // + mi*16
    const int a_chg = lane >> 4;                    // 0/1 -> +k8
    const int b_g = lane >> 3;
    const int b_row = wn * 64 + ((b_g >> 1) << 3) + (lane & 7);  // + nb*16
    const int b_chg = b_g & 1;

    for (int i = 0; i < nK; i++) {
        asm volatile("cp.async.wait_group 2;" ::: "memory");
        __syncthreads();
        if (i + 3 < nK) gemm_load_stage(A, B, K3, m0, n0, tid, sb, (i + 3) & 3, i + 3);
        CP_COMMIT();

        const uint32_t abase = sb + (i & 3) * GSTAGE_BYTES;
        const uint32_t bbase = abase + 8192;
#pragma unroll
        for (int kk = 0; kk < 2; kk++) {
            uint32_t af[2][4];
#pragma unroll
            for (int mi = 0; mi < 2; mi++) {
                const int row = a_row + mi * 16;
                const int ch = kk * 2 + a_chg;
                const int csw = ch ^ ((row >> 1) & 3);
                ldsm_x4(abase + row * 64 + csw * 16,
                        af[mi][0], af[mi][1], af[mi][2], af[mi][3]);
            }
            uint32_t bf[4][4];
#pragma unroll
            for (int nb = 0; nb < 4; nb++) {
                const int row = b_row + nb * 16;
                const int ch = kk * 2 + b_chg;
                const int csw = ch ^ ((row >> 1) & 3);
                ldsm_x4(bbase + row * 64 + csw * 16,
                        bf[nb][0], bf[nb][1], bf[nb][2], bf[nb][3]);
            }
#pragma unroll
            for (int mi = 0; mi < 2; mi++)
#pragma unroll
                for (int nb = 0; nb < 4; nb++) {
                    mma_bf16(acc[mi][nb * 2 + 0], af[mi], bf[nb][0], bf[nb][1]);
                    mma_bf16(acc[mi][nb * 2 + 1], af[mi], bf[nb][2], bf[nb][3]);
                }
        }
        __syncthreads();
    }

    // epilogue: direct float2 stores
    const int erow = (lane >> 2);
    const int ecol = (lane & 3) << 1;
#pragma unroll
    for (int mi = 0; mi < 2; mi++) {
        const int r = m0 + wm * 32 + mi * 16 + erow;
#pragma unroll
        for (int f = 0; f < 8; f++) {
            const int c = n0 + wn * 64 + (f >> 1) * 16 + (f & 1) * 8 + ecol;
            if (c < Nvalid) {
                *(float2*)(C + (size_t)r * Nstride + c) =
                    make_float2(acc[mi][f][0], acc[mi][f][1]);
                *(float2*)(C + (size_t)(r + 8) * Nstride + c) =
                    make_float2(acc[mi][f][2], acc[mi][f][3]);
            }
        }
    }
}

// ---------------- depthwise causal conv (K=4) + bias + silu ----------------
__global__ void conv_silu_kernel(const float* __restrict__ cw, const float* __restrict__ cb) {
    const int c = blockIdx.x * 256 + threadIdx.x;
    const int t = blockIdx.y;
    float acc = cb[c];
#pragma unroll
    for (int k = 0; k < 4; k++) {
        const int tt = t - 3 + k;
        if (tt >= 0) acc += g_proj[(size_t)tt * PROJD + INTERD + c] * cw[c * 4 + k];
    }
    g_hconv[(size_t)t * CONVD + c] = acc / (1.f + __expf(-acc));
}

// ---------------- dt2 = softplus(dt + dt_bias) ----------------
__global__ void dt2_kernel(const float* __restrict__ dt_bias) {
    const int idx = blockIdx.x * 256 + threadIdx.x;
    const int t = idx >> 6;
    const int h = idx & 63;
    const float x = g_proj[(size_t)t * PROJD + DTOFF + h] + dt_bias[h];
    g_dt2[idx] = (x > 20.f) ? x : log1pf(expf(x));
}

// ---------------- per-(head,chunk) inclusive cumsum of A*dt2 ----------------
__global__ void acum_kernel(const float* __restrict__ A_log) {
    const int chunk = blockIdx.x;
    const int h = blockIdx.y;
    const int tid = threadIdx.x;
    const float Ah = -expf(A_log[h]);
    __shared__ float s[CSZ];
    const int t = chunk * CSZ + tid;
    s[tid] = Ah * g_dt2[t * NH + h];
    for (int off = 1; off < CSZ; off <<= 1) {
        __syncthreads();
        const float v = (tid >= off) ? s[tid - off] : 0.f;
        __syncthreads();
        s[tid] += v;
    }
    g_acum[h * SS + t] = s[tid];
}

// ---------------- fused SSD per (chunk, head) ----------------
#define SSD_SMEM_FLOATS (8320 + 4096 + 4112 + 16640 + 256)
__global__ __launch_bounds__(256, 1)
void ssd_kernel(const float* __restrict__ Dp) {
    extern __shared__ float sm[];
    float* Bts = sm;                         // [128][65]
    float* Xt  = sm + 8320;                  // [64][64]
    float* Cs  = sm + 8320 + 4096;           // [16][257]
    float* Gw  = sm + 8320 + 4096 + 4112;    // [256][65]
    float* acs = Gw + 16640;                 // [256]

    const int tid = threadIdx.x;
    const int chunk = blockIdx.x;
    const int h = blockIdx.y;
    const int t0 = chunk * CSZ;
    const int grp = h & 7;
    const int Bbase = INTERD + grp * SN;
    const int Cbase = INTERD + NG * SN + grp * SN;
    const int tx = tid & 15, ty = tid >> 4;

    acs[tid] = g_acum[h * SS + t0 + tid];
    __syncthreads();
    const float alast = acs[CSZ - 1];

    float yacc[64];
#pragma unroll
    for (int p = 0; p < 64; p++) yacc[p] = 0.f;

    for (int jt = 0; jt < 4; ++jt) {
        const int jbase = jt * 64;
#pragma unroll
        for (int it = 0; it < 8; ++it) {
            const int idx = it * 256 + tid;
            const int jj = idx >> 5;
            const int n4 = (idx & 31) << 2;
            const float4 v = *(const float4*)(g_hconv + (size_t)(t0 + jbase + jj) * CONVD + Bbase + n4);
            Bts[(n4 + 0) * 65 + jj] = v.x; Bts[(n4 + 1) * 65 + jj] = v.y;
            Bts[(n4 + 2) * 65 + jj] = v.z; Bts[(n4 + 3) * 65 + jj] = v.w;
        }
#pragma unroll
        for (int it = 0; it < 4; ++it) {
            const int idx = it * 256 + tid;
            const int jj = idx >> 4;
            const int p4 = (idx & 15) << 2;
            const int tj = t0 + jbase + jj;
            float4 v = *(const float4*)(g_hconv + (size_t)tj * CONVD + h * HP + p4);
            const float sc = g_dt2[tj * NH + h];
            v.x *= sc; v.y *= sc; v.z *= sc; v.w *= sc;
            *(float4*)(Xt + jj * 64 + p4) = v;
        }
        __syncthreads();

        float gacc[64];
#pragma unroll
        for (int q = 0; q < 64; q++) gacc[q] = 0.f;
        for (int n0 = 0; n0 < SN; n0 += 16) {
#pragma unroll
            for (int it = 0; it < 16; ++it) {
                const int idx = it * 256 + tid;
                const int i = idx >> 4;
                const int nn = idx & 15;
                Cs[nn * 257 + i] = g_hconv[(size_t)(t0 + i) * CONVD + Cbase + n0 + nn];
            }
            __syncthreads();
#pragma unroll
            for (int kk = 0; kk < 16; kk++) {
                float a[16];
#pragma unroll
                for (int u = 0; u < 16; u++) a[u] = Cs[kk * 257 + ty * 16 + u];
                const float* br = Bts + (n0 + kk) * 65 + tx * 4;
                const float b0 = br[0], b1 = br[1], b2 = br[2], b3 = br[3];
#pragma unroll
                for (int u = 0; u < 16; u++) {
                    gacc[u * 4 + 0] += a[u] * b0;
                    gacc[u * 4 + 1] += a[u] * b1;
                    gacc[u * 4 + 2] += a[u] * b2;
                    gacc[u * 4 + 3] += a[u] * b3;
                }
            }
            __syncthreads();
        }
#pragma unroll
        for (int u = 0; u < 16; u++) {
            const int i = ty * 16 + u;
            const float ai = acs[i];
#pragma unroll
            for (int v = 0; v < 4; v++) {
                const int j = tx * 4 + v;
                const int jg = jbase + j;
                const float d = ai - acs[jg];
                float w = __expf(d + alast);
                if (jg <= i) w += __expf(d);
                Gw[i * 65 + j] = gacc[u * 4 + v] * w;
            }
        }
        __syncthreads();
#pragma unroll 4
        for (int j = 0; j < 64; j++) {
            const float gv = Gw[tid * 65 + j];
            const float4* xr = (const float4*)(Xt + (j << 6));
#pragma unroll
            for (int p4 = 0; p4 < 16; p4++) {
                const float4 xv = xr[p4];
                yacc[p4 * 4 + 0] += gv * xv.x;
                yacc[p4 * 4 + 1] += gv * xv.y;
                yacc[p4 * 4 + 2] += gv * xv.z;
                yacc[p4 * 4 + 3] += gv * xv.w;
            }
        }
        __syncthreads();
    }

    const float Dh = Dp[h];
    const float4* hrow = (const float4*)(g_hconv + (size_t)(t0 + tid) * CONVD + h * HP);
#pragma unroll
    for (int p4 = 0; p4 < 16; p4++) {
        const float4 hv = hrow[p4];
        yacc[p4 * 4 + 0] += Dh * hv.x;
        yacc[p4 * 4 + 1] += Dh * hv.y;
        yacc[p4 * 4 + 2] += Dh * hv.z;
        yacc[p4 * 4 + 3] += Dh * hv.w;
    }
#pragma unroll
    for (int p = 0; p < 64; p++) Gw[tid * 65 + p] = yacc[p];
    __syncthreads();
#pragma unroll
    for (int it = 0; it < 16; ++it) {
        const int idx = it * 256 + tid;
        const int i = idx >> 4;
        const int p4 = (idx & 15) << 2;
        float4 v;
        v.x = Gw[i * 65 + p4 + 0]; v.y = Gw[i * 65 + p4 + 1];
        v.z = Gw[i * 65 + p4 + 2]; v.w = Gw[i * 65 + p4 + 3];
        *(float4*)(g_y + (size_t)(t0 + i) * INTERD + h * HP + p4) = v;
    }
}

// ---------------- gate silu + RMSNorm ----------------
__global__ void norm_kernel(const float* __restrict__ norm_w) {
    const int t = blockIdx.x;
    const int tid = threadIdx.x;
    __shared__ float red[256];
    float local = 0.f;
    for (int c = tid; c < INTERD; c += 256) {
        const float g = g_proj[(size_t)t * PROJD + c];
        const float yv = g_y[(size_t)t * INTERD + c];
        const float yg = yv * (g / (1.f + __expf(-g)));
        g_y[(size_t)t * INTERD + c] = yg;
        local += yg * yg;
    }
    red[tid] = local;
    __syncthreads();
    for (int s = 128; s > 0; s >>= 1) {
        if (tid < s) red[tid] += red[tid + s];
        __syncthreads();
    }
    const float rstd = rsqrtf(red[0] / (float)INTERD + 1e-6f);
    for (int c = tid; c < INTERD; c += 256) {
        g_norm[(size_t)t * INTERD + c] = norm_w[c] * g_y[(size_t)t * INTERD + c] * rstd;
    }
}

// ---------------- launch ----------------
extern "C" void kernel_launch(void* const* d_in, const int* in_sizes, int n_in,
                              void* d_out, int out_size) {
    (void)in_sizes; (void)n_in; (void)out_size;
    const float* x       = (const float*)d_in[0];
    const float* w_in    = (const float*)d_in[1];
    const float* conv_w  = (const float*)d_in[2];
    const float* conv_b  = (const float*)d_in[3];
    const float* dt_bias = (const float*)d_in[4];
    const float* A_log   = (const float*)d_in[5];
    const float* Dv      = (const float*)d_in[6];
    const float* norm_w  = (const float*)d_in[7];
    const float* w_out   = (const float*)d_in[8];
    float* out = (float*)d_out;

    float* p_proj = nullptr;
    float* p_norm = nullptr;
    __nv_bfloat16* p_Apack = nullptr;
    __nv_bfloat16* p_B1 = nullptr;
    __nv_bfloat16* p_B2 = nullptr;
    cudaGetSymbolAddress((void**)&p_proj, g_proj);
    cudaGetSymbolAddress((void**)&p_norm, g_norm);
    cudaGetSymbolAddress((void**)&p_Apack, g_Apack);
    cudaGetSymbolAddress((void**)&p_B1, g_B1);
    cudaGetSymbolAddress((void**)&p_B2, g_B2);

    cudaFuncSetAttribute(tgemm, cudaFuncAttributeMaxDynamicSharedMemorySize, GEMM_DYN_SMEM);
    cudaFuncSetAttribute(ssd_kernel, cudaFuncAttributeMaxDynamicSharedMemorySize,
                         SSD_SMEM_FLOATS * (int)sizeof(float));

    // --- GEMM1: proj = X @ W_in^T via split-bf16 HMMA ---
    pack_split<<<2048, 256>>>(x, p_Apack, SS, SS, EMB, 0);
    pack_split<<<4096, 256>>>(w_in, p_B1, PROJD, PROJPAD, EMB, 1);
    tgemm<<<dim3(SS / 128, PROJPAD / 128), 256, GEMM_DYN_SMEM>>>(
        p_Apack, p_B1, p_proj, 3 * EMB, PROJD, PROJD);

    // --- elementwise / scan stages ---
    conv_silu_kernel<<<dim3(CONVD / 256, SS), 256>>>(conv_w, conv_b);
    dt2_kernel<<<(SS * NH) / 256, 256>>>(dt_bias);
    acum_kernel<<<dim3(NCH, NH), 256>>>(A_log);
    ssd_kernel<<<dim3(NCH, NH), 256, SSD_SMEM_FLOATS * (int)sizeof(float)>>>(Dv);
    norm_kernel<<<SS, 256>>>(norm_w);

    // --- GEMM2: out = normed @ W_out^T via split-bf16 HMMA ---
    pack_split<<<4096, 256>>>(p_norm, p_Apack, SS, SS, INTERD, 0);
    pack_split<<<2048, 256>>>(w_out, p_B2, EMB, EMB, INTERD, 1);
    tgemm<<<dim3(SS / 128, EMB / 128), 256, GEMM_DYN_SMEM>>>(
        p_Apack, p_B2, out, 3 * INTERD, EMB, EMB);
}

// round 4
// speedup vs baseline: 3.9441x; 1.0650x over previous
#include <cuda_runtime.h>
#include <cuda_bf16.h>
#include <cstdint>
#include <cstddef>

// ---------------- problem constants ----------------
#define SS      4096
#define EMB     2048
#define PROJD   10304
#define PROJPAD 10368
#define INTERD  4096
#define CONVD   6144
#define NH      64
#define HP      64
#define SN      128
#define NG      8
#define CSZ     256
#define NCH     16
#define DTOFF   10240

// ---------------- scratch ----------------
__device__ float g_proj[(size_t)SS * PROJD];
__device__ float g_hconv[(size_t)SS * CONVD];
__device__ float g_dt2[SS * NH];
__device__ float g_acum[NH * SS];
__device__ float g_y[(size_t)SS * INTERD];
__device__ __nv_bfloat16 g_Apack[(size_t)SS * 3 * INTERD];
__device__ __nv_bfloat16 g_B1[(size_t)PROJPAD * 3 * EMB];
__device__ __nv_bfloat16 g_B2[(size_t)EMB * 3 * INTERD];

// ================= helpers =================
__device__ __forceinline__ uint32_t smem_u32(const void* p) {
    uint32_t a;
    asm("{ .reg .u64 t; cvta.to.shared.u64 t, %1; cvt.u32.u64 %0, t; }" : "=r"(a) : "l"(p));
    return a;
}
__device__ __forceinline__ void cp_async16(uint32_t saddr, const void* g) {
    asm volatile("cp.async.cg.shared.global [%0], [%1], 16;" :: "r"(saddr), "l"(g) : "memory");
}
#define CP_COMMIT() asm volatile("cp.async.commit_group;" ::: "memory")

__device__ __forceinline__ void ldsm_x4(uint32_t addr, uint32_t& r0, uint32_t& r1,
                                        uint32_t& r2, uint32_t& r3) {
    asm volatile("ldmatrix.sync.aligned.m8n8.x4.shared.b16 {%0,%1,%2,%3}, [%4];"
                 : "=r"(r0), "=r"(r1), "=r"(r2), "=r"(r3) : "r"(addr));
}
__device__ __forceinline__ void mma_bf16(float* d, const uint32_t* a, uint32_t b0, uint32_t b1) {
    asm volatile(
        "mma.sync.aligned.m16n8k16.row.col.f32.bf16.bf16.f32 "
        "{%0,%1,%2,%3}, {%4,%5,%6,%7}, {%8,%9}, {%0,%1,%2,%3};"
        : "+f"(d[0]), "+f"(d[1]), "+f"(d[2]), "+f"(d[3])
        : "r"(a[0]), "r"(a[1]), "r"(a[2]), "r"(a[3]), "r"(b0), "r"(b1));
}

// ================= split-pack (vectorized, row-ranged) =================
// mode 0 (A): [hi | lo | hi]; mode 1 (B): [hi | hi | lo]; rows >= srcRows -> zeros
__global__ void pack_split(const float* __restrict__ src, __nv_bfloat16* __restrict__ dst,
                           int srcRows, int rowStart, int rowEnd, int K, int mode) {
    const int K8 = K >> 3;
    const size_t total = (size_t)(rowEnd - rowStart) * K8;
    for (size_t v = (size_t)blockIdx.x * 256 + threadIdx.x; v < total;
         v += (size_t)gridDim.x * 256) {
        const int r = rowStart + (int)(v / K8);
        const int k = (int)(v % K8) << 3;
        float x[8];
        if (r < srcRows) {
            const float4 f0 = *(const float4*)(src + (size_t)r * K + k);
            const float4 f1 = *(const float4*)(src + (size_t)r * K + k + 4);
            x[0] = f0.x; x[1] = f0.y; x[2] = f0.z; x[3] = f0.w;
            x[4] = f1.x; x[5] = f1.y; x[6] = f1.z; x[7] = f1.w;
        } else {
#pragma unroll
            for (int i = 0; i < 8; i++) x[i] = 0.f;
        }
        union { __nv_bfloat16 h[8]; uint4 u; } uh, ul;
#pragma unroll
        for (int i = 0; i < 8; i++) {
            uh.h[i] = __float2bfloat16(x[i]);
            ul.h[i] = __float2bfloat16(x[i] - __bfloat162float(uh.h[i]));
        }
        const size_t ro = (size_t)r * 3 * K + k;
        *(uint4*)(dst + ro) = uh.u;
        if (mode == 0) {
            *(uint4*)(dst + ro + K) = ul.u;
            *(uint4*)(dst + ro + 2 * K) = uh.u;
        } else {
            *(uint4*)(dst + ro + K) = uh.u;
            *(uint4*)(dst + ro + 2 * K) = ul.u;
        }
    }
}

// ================= HMMA GEMM: C[M,N] = A[M,K3] * B[N,K3]^T =================
// bf16 in, fp32 accum. CTA 128x128, BK=64, 4-stage cp.async pipeline, CTA swizzle.
#define GSTAGES 4
#define GSTAGE_BYTES 32768          // A 16KB + B 16KB
#define GEMM_DYN_SMEM (GSTAGES * GSTAGE_BYTES)

__device__ __forceinline__ void gemm_load_stage(
    const __nv_bfloat16* __restrict__ A, const __nv_bfloat16* __restrict__ B,
    int K3, int m0, int n0, int tid, uint32_t sb, int stage, int kk) {
    const uint32_t abase = sb + stage * GSTAGE_BYTES;
    const uint32_t bbase = abase + 16384;
    const int k0 = kk * 64;
#pragma unroll
    for (int it = 0; it < 4; it++) {
        const int idx = it * 256 + tid;          // 0..1023
        const int row = idx >> 3;
        const int ch = idx & 7;
        const int csw = ch ^ (row & 7);
        cp_async16(abase + row * 128 + csw * 16,
                   A + (size_t)(m0 + row) * K3 + k0 + ch * 8);
    }
#pragma unroll
    for (int it = 0; it < 4; it++) {
        const int idx = it * 256 + tid;
        const int row = idx >> 3;
        const int ch = idx & 7;
        const int csw = ch ^ (row & 7);
        cp_async16(bbase + row * 128 + csw * 16,
                   B + (size_t)(n0 + row) * K3 + k0 + ch * 8);
    }
}

__global__ __launch_bounds__(256)
void tgemm(const __nv_bfloat16* __restrict__ A, const __nv_bfloat16* __restrict__ B,
           float* __restrict__ C, int K3, int Nvalid, int Nstride) {
    extern __shared__ char dynsm[];
    const uint32_t sb = smem_u32(dynsm);
    const int tid = threadIdx.x;
    const int lane = tid & 31;
    const int wid = tid >> 5;
    const int wm = wid & 3;
    const int wn = wid >> 2;

    // CTA swizzle: groups of 16 M-blocks iterate over all N (L2-friendly)
    const int gridM = gridDim.x;
    const int gridN = gridDim.y;
    const int bid = blockIdx.y * gridM + blockIdx.x;
    const int GM = 16;
    const int group = bid / (GM * gridN);
    const int rem = bid - group * (GM * gridN);
    const int m0 = (group * GM + (rem % GM)) * 128;
    const int n0 = (rem / GM) * 128;
    const int nK = K3 >> 6;

    float acc[2][8][4];
#pragma unroll
    for (int i = 0; i < 2; i++)
#pragma unroll
        for (int j = 0; j < 8; j++)
#pragma unroll
            for (int q = 0; q < 4; q++) acc[i][j][q] = 0.f;

    gemm_load_stage(A, B, K3, m0, n0, tid, sb, 0, 0); CP_COMMIT();
    gemm_load_stage(A, B, K3, m0, n0, tid, sb, 1, 1); CP_COMMIT();
    gemm_load_stage(A, B, K3, m0, n0, tid, sb, 2, 2); CP_COMMIT();

    const int a_row = wm * 32 + (lane & 15);
    const int a_chg = lane >> 4;
    const int b_g = lane >> 3;
    const int b_row = wn * 64 + ((b_g >> 1) << 3) + (lane & 7);
    const int b_chg = b_g & 1;

    for (int i = 0; i < nK; i++) {
        asm volatile("cp.async.wait_group 2;" ::: "memory");
        __syncthreads();
        if (i + 3 < nK) gemm_load_stage(A, B, K3, m0, n0, tid, sb, (i + 3) & 3, i + 3);
        CP_COMMIT();

        const uint32_t abase = sb + (i & 3) * GSTAGE_BYTES;
        const uint32_t bbase = abase + 16384;
#pragma unroll
        for (int kk = 0; kk < 4; kk++) {
            uint32_t af[2][4];
#pragma unroll
            for (int mi = 0; mi < 2; mi++) {
                const int row = a_row + mi * 16;
                const int ch = kk * 2 + a_chg;
                const int csw = ch ^ (row & 7);
                ldsm_x4(abase + row * 128 + csw * 16,
                        af[mi][0], af[mi][1], af[mi][2], af[mi][3]);
            }
            uint32_t bf[4][4];
#pragma unroll
            for (int nb = 0; nb < 4; nb++) {
                const int row = b_row + nb * 16;
                const int ch = kk * 2 + b_chg;
                const int csw = ch ^ (row & 7);
                ldsm_x4(bbase + row * 128 + csw * 16,
                        bf[nb][0], bf[nb][1], bf[nb][2], bf[nb][3]);
            }
#pragma unroll
            for (int mi = 0; mi < 2; mi++)
#pragma unroll
                for (int nb = 0; nb < 4; nb++) {
                    mma_bf16(acc[mi][nb * 2 + 0], af[mi], bf[nb][0], bf[nb][1]);
                    mma_bf16(acc[mi][nb * 2 + 1], af[mi], bf[nb][2], bf[nb][3]);
                }
        }
        __syncthreads();
    }

    const int erow = (lane >> 2);
    const int ecol = (lane & 3) << 1;
#pragma unroll
    for (int mi = 0; mi < 2; mi++) {
        const int r = m0 + wm * 32 + mi * 16 + erow;
#pragma unroll
        for (int f = 0; f < 8; f++) {
            const int c = n0 + wn * 64 + (f >> 1) * 16 + (f & 1) * 8 + ecol;
            if (c < Nvalid) {
                *(float2*)(C + (size_t)r * Nstride + c) =
                    make_float2(acc[mi][f][0], acc[mi][f][1]);
                *(float2*)(C + (size_t)(r + 8) * Nstride + c) =
                    make_float2(acc[mi][f][2], acc[mi][f][3]);
            }
        }
    }
}

// ---------------- depthwise causal conv (K=4) + bias + silu, 4 t/thread ----------------
__global__ void conv_silu_kernel(const float* __restrict__ cw, const float* __restrict__ cb) {
    const int c = blockIdx.x * 256 + threadIdx.x;
    const int tb = blockIdx.y * 4;
    const float w0 = cw[c * 4 + 0], w1 = cw[c * 4 + 1],
                w2 = cw[c * 4 + 2], w3 = cw[c * 4 + 3];
    const float bias = cb[c];
    float v[7];
#pragma unroll
    for (int k = 0; k < 7; k++) {
        const int tt = tb - 3 + k;
        v[k] = (tt >= 0) ? g_proj[(size_t)tt * PROJD + INTERD + c] : 0.f;
    }
#pragma unroll
    for (int j = 0; j < 4; j++) {
        const float a = bias + v[j] * w0 + v[j + 1] * w1 + v[j + 2] * w2 + v[j + 3] * w3;
        g_hconv[(size_t)(tb + j) * CONVD + c] = a / (1.f + __expf(-a));
    }
}

// ---------------- fused softplus(dt)+cumsum per (chunk, head) ----------------
__global__ void dtacum_kernel(const float* __restrict__ dt_bias,
                              const float* __restrict__ A_log) {
    const int chunk = blockIdx.x;
    const int h = blockIdx.y;
    const int tid = threadIdx.x;
    const float Ah = -expf(A_log[h]);
    const float bias = dt_bias[h];
    __shared__ float s[CSZ];
    const int t = chunk * CSZ + tid;
    const float x = g_proj[(size_t)t * PROJD + DTOFF + h] + bias;
    const float dt2 = (x > 20.f) ? x : log1pf(expf(x));
    g_dt2[t * NH + h] = dt2;
    s[tid] = Ah * dt2;
    for (int off = 1; off < CSZ; off <<= 1) {
        __syncthreads();
        const float v = (tid >= off) ? s[tid - off] : 0.f;
        __syncthreads();
        s[tid] += v;
    }
    g_acum[h * SS + t] = s[tid];
}

// ---------------- fused SSD per (chunk, head) ----------------
#define SSD_SMEM_FLOATS (8320 + 4096 + 4112 + 16640 + 256)
__global__ __launch_bounds__(256, 1)
void ssd_kernel(const float* __restrict__ Dp) {
    extern __shared__ float sm[];
    float* Bts = sm;                         // [128][65]
    float* Xt  = sm + 8320;                  // [64][64]
    float* Cs  = sm + 8320 + 4096;           // [16][257]
    float* Gw  = sm + 8320 + 4096 + 4112;    // [256][65]
    float* acs = Gw + 16640;                 // [256]

    const int tid = threadIdx.x;
    const int chunk = blockIdx.x;
    const int h = blockIdx.y;
    const int t0 = chunk * CSZ;
    const int grp = h & 7;
    const int Bbase = INTERD + grp * SN;
    const int Cbase = INTERD + NG * SN + grp * SN;
    const int tx = tid & 15, ty = tid >> 4;

    acs[tid] = g_acum[h * SS + t0 + tid];
    __syncthreads();
    const float alast = acs[CSZ - 1];

    float yacc[64];
#pragma unroll
    for (int p = 0; p < 64; p++) yacc[p] = 0.f;

    for (int jt = 0; jt < 4; ++jt) {
        const int jbase = jt * 64;
#pragma unroll
        for (int it = 0; it < 8; ++it) {
            const int idx = it * 256 + tid;
            const int jj = idx >> 5;
            const int n4 = (idx & 31) << 2;
            const float4 v = *(const float4*)(g_hconv + (size_t)(t0 + jbase + jj) * CONVD + Bbase + n4);
            Bts[(n4 + 0) * 65 + jj] = v.x; Bts[(n4 + 1) * 65 + jj] = v.y;
            Bts[(n4 + 2) * 65 + jj] = v.z; Bts[(n4 + 3) * 65 + jj] = v.w;
        }
#pragma unroll
        for (int it = 0; it < 4; ++it) {
            const int idx = it * 256 + tid;
            const int jj = idx >> 4;
            const int p4 = (idx & 15) << 2;
            const int tj = t0 + jbase + jj;
            float4 v = *(const float4*)(g_hconv + (size_t)tj * CONVD + h * HP + p4);
            const float sc = g_dt2[tj * NH + h];
            v.x *= sc; v.y *= sc; v.z *= sc; v.w *= sc;
            *(float4*)(Xt + jj * 64 + p4) = v;
        }
        __syncthreads();

        float gacc[64];
#pragma unroll
        for (int q = 0; q < 64; q++) gacc[q] = 0.f;
        for (int n0 = 0; n0 < SN; n0 += 16) {
#pragma unroll
            for (int it = 0; it < 16; ++it) {
                const int idx = it * 256 + tid;
                const int i = idx >> 4;
                const int nn = idx & 15;
                Cs[nn * 257 + i] = g_hconv[(size_t)(t0 + i) * CONVD + Cbase + n0 + nn];
            }
            __syncthreads();
#pragma unroll
            for (int kk = 0; kk < 16; kk++) {
                float a[16];
#pragma unroll
                for (int u = 0; u < 16; u++) a[u] = Cs[kk * 257 + ty * 16 + u];
                const float* br = Bts + (n0 + kk) * 65 + tx * 4;
                const float b0 = br[0], b1 = br[1], b2 = br[2], b3 = br[3];
#pragma unroll
                for (int u = 0; u < 16; u++) {
                    gacc[u * 4 + 0] += a[u] * b0;
                    gacc[u * 4 + 1] += a[u] * b1;
                    gacc[u * 4 + 2] += a[u] * b2;
                    gacc[u * 4 + 3] += a[u] * b3;
                }
            }
            __syncthreads();
        }
#pragma unroll
        for (int u = 0; u < 16; u++) {
            const int i = ty * 16 + u;
            const float ai = acs[i];
#pragma unroll
            for (int v = 0; v < 4; v++) {
                const int j = tx * 4 + v;
                const int jg = jbase + j;
                const float d = ai - acs[jg];
                float w = __expf(d + alast);
                if (jg <= i) w += __expf(d);
                Gw[i * 65 + j] = gacc[u * 4 + v] * w;
            }
        }
        __syncthreads();
#pragma unroll 4
        for (int j = 0; j < 64; j++) {
            const float gv = Gw[tid * 65 + j];
            const float4* xr = (const float4*)(Xt + (j << 6));
#pragma unroll
            for (int p4 = 0; p4 < 16; p4++) {
                const float4 xv = xr[p4];
                yacc[p4 * 4 + 0] += gv * xv.x;
                yacc[p4 * 4 + 1] += gv * xv.y;
                yacc[p4 * 4 + 2] += gv * xv.z;
                yacc[p4 * 4 + 3] += gv * xv.w;
            }
        }
        __syncthreads();
    }

    const float Dh = Dp[h];
    const float4* hrow = (const float4*)(g_hconv + (size_t)(t0 + tid) * CONVD + h * HP);
#pragma unroll
    for (int p4 = 0; p4 < 16; p4++) {
        const float4 hv = hrow[p4];
        yacc[p4 * 4 + 0] += Dh * hv.x;
        yacc[p4 * 4 + 1] += Dh * hv.y;
        yacc[p4 * 4 + 2] += Dh * hv.z;
        yacc[p4 * 4 + 3] += Dh * hv.w;
    }
#pragma unroll
    for (int p = 0; p < 64; p++) Gw[tid * 65 + p] = yacc[p];
    __syncthreads();
#pragma unroll
    for (int it = 0; it < 16; ++it) {
        const int idx = it * 256 + tid;
        const int i = idx >> 4;
        const int p4 = (idx & 15) << 2;
        float4 v;
        v.x = Gw[i * 65 + p4 + 0]; v.y = Gw[i * 65 + p4 + 1];
        v.z = Gw[i * 65 + p4 + 2]; v.w = Gw[i * 65 + p4 + 3];
        *(float4*)(g_y + (size_t)(t0 + i) * INTERD + h * HP + p4) = v;
    }
}

// ---------------- gate silu + RMSNorm + split-bf16 A-pack (fused) ----------------
__global__ void norm_pack_kernel(const float* __restrict__ norm_w) {
    const int t = blockIdx.x;
    const int tid = threadIdx.x;
    __shared__ float red[256];
    __shared__ float yg_s[INTERD];
    float local = 0.f;
    for (int c = tid; c < INTERD; c += 256) {
        const float g = g_proj[(size_t)t * PROJD + c];
        const float yv = g_y[(size_t)t * INTERD + c];
        const float yg = yv * (g / (1.f + __expf(-g)));
        yg_s[c] = yg;
        local += yg * yg;
    }
    red[tid] = local;
    __syncthreads();
    for (int s = 128; s > 0; s >>= 1) {
        if (tid < s) red[tid] += red[tid + s];
        __syncthreads();
    }
    const float rstd = rsqrtf(red[0] / (float)INTERD + 1e-6f);
    __nv_bfloat16* dst = g_Apack + (size_t)t * 3 * INTERD;
    for (int c = tid * 4; c < INTERD; c += 1024) {
        union { __nv_bfloat16 h[4]; uint2 u; } uh, ul;
#pragma unroll
        for (int i = 0; i < 4; i++) {
            const float v = norm_w[c + i] * yg_s[c + i] * rstd;
            uh.h[i] = __float2bfloat16(v);
            ul.h[i] = __float2bfloat16(v - __bfloat162float(uh.h[i]));
        }
        *(uint2*)(dst + c) = uh.u;
        *(uint2*)(dst + INTERD + c) = ul.u;
        *(uint2*)(dst + 2 * INTERD + c) = uh.u;
    }
}

// ---------------- launch ----------------
extern "C" void kernel_launch(void* const* d_in, const int* in_sizes, int n_in,
                              void* d_out, int out_size) {
    (void)in_sizes; (void)n_in; (void)out_size;
    const float* x       = (const float*)d_in[0];
    const float* w_in    = (const float*)d_in[1];
    const float* conv_w  = (const float*)d_in[2];
    const float* conv_b  = (const float*)d_in[3];
    const float* dt_bias = (const float*)d_in[4];
    const float* A_log   = (const float*)d_in[5];
    const float* Dv      = (const float*)d_in[6];
    const float* norm_w  = (const float*)d_in[7];
    const float* w_out   = (const float*)d_in[8];
    float* out = (float*)d_out;

    float* p_proj = nullptr;
    __nv_bfloat16* p_Apack = nullptr;
    __nv_bfloat16* p_B1 = nullptr;
    __nv_bfloat16* p_B2 = nullptr;
    cudaGetSymbolAddress((void**)&p_proj, g_proj);
    cudaGetSymbolAddress((void**)&p_Apack, g_Apack);
    cudaGetSymbolAddress((void**)&p_B1, g_B1);
    cudaGetSymbolAddress((void**)&p_B2, g_B2);

    cudaFuncSetAttribute(tgemm, cudaFuncAttributeMaxDynamicSharedMemorySize, GEMM_DYN_SMEM);
    cudaFuncSetAttribute(ssd_kernel, cudaFuncAttributeMaxDynamicSharedMemorySize,
                         SSD_SMEM_FLOATS * (int)sizeof(float));

    // --- GEMM1 packs (B pack split into 2 so tgemm is the 4th launch for ncu) ---
    pack_split<<<2048, 256>>>(x, p_Apack, SS, 0, SS, EMB, 0);
    pack_split<<<2048, 256>>>(w_in, p_B1, PROJD, 0, PROJPAD / 2, EMB, 1);
    pack_split<<<2048, 256>>>(w_in, p_B1, PROJD, PROJPAD / 2, PROJPAD, EMB, 1);
    // --- GEMM1: proj = X @ W_in^T ---
    tgemm<<<dim3(SS / 128, PROJPAD / 128), 256, GEMM_DYN_SMEM>>>(
        p_Apack, p_B1, p_proj, 3 * EMB, PROJD, PROJD);

    // --- elementwise / scan stages ---
    conv_silu_kernel<<<dim3(CONVD / 256, SS / 4), 256>>>(conv_w, conv_b);
    dtacum_kernel<<<dim3(NCH, NH), CSZ>>>(dt_bias, A_log);
    ssd_kernel<<<dim3(NCH, NH), 256, SSD_SMEM_FLOATS * (int)sizeof(float)>>>(Dv);
    norm_pack_kernel<<<SS, 256>>>(norm_w);

    // --- GEMM2: out = normed @ W_out^T ---
    pack_split<<<2048, 256>>>(w_out, p_B2, EMB, 0, EMB, INTERD, 1);
    tgemm<<<dim3(SS / 128, EMB / 128), 256, GEMM_DYN_SMEM>>>(
        p_Apack, p_B2, out, 3 * INTERD, EMB, EMB);
}

// round 5
// speedup vs baseline: 4.3473x; 1.1022x over previous
#include <cuda_runtime.h>
#include <cuda_bf16.h>
#include <cstdint>
#include <cstddef>

// ---------------- problem constants ----------------
#define SS      4096
#define EMB     2048
#define PROJD   10304
#define PROJPAD 10368
#define INTERD  4096
#define CONVD   6144
#define NH      64
#define HP      64
#define SN      128
#define NG      8
#define CSZ     256
#define NCH     16
#define DTOFF   10240

// ---------------- scratch ----------------
__device__ float g_proj[(size_t)SS * PROJD];
__device__ float g_hconv[(size_t)SS * CONVD];
__device__ float g_dt2[SS * NH];
__device__ float g_acum[NH * SS];
__device__ float g_y[(size_t)SS * INTERD];
__device__ __nv_bfloat16 g_Apack[(size_t)SS * 3 * INTERD];
__device__ __nv_bfloat16 g_B1[(size_t)PROJPAD * 3 * EMB];
__device__ __nv_bfloat16 g_B2[(size_t)EMB * 3 * INTERD];

// ================= helpers =================
__device__ __forceinline__ uint32_t smem_u32(const void* p) {
    uint32_t a;
    asm("{ .reg .u64 t; cvta.to.shared.u64 t, %1; cvt.u32.u64 %0, t; }" : "=r"(a) : "l"(p));
    return a;
}
__device__ __forceinline__ void cp_async16(uint32_t saddr, const void* g) {
    asm volatile("cp.async.cg.shared.global [%0], [%1], 16;" :: "r"(saddr), "l"(g) : "memory");
}
#define CP_COMMIT() asm volatile("cp.async.commit_group;" ::: "memory")

__device__ __forceinline__ void ldsm_x4(uint32_t addr, uint32_t& r0, uint32_t& r1,
                                        uint32_t& r2, uint32_t& r3) {
    asm volatile("ldmatrix.sync.aligned.m8n8.x4.shared.b16 {%0,%1,%2,%3}, [%4];"
                 : "=r"(r0), "=r"(r1), "=r"(r2), "=r"(r3) : "r"(addr));
}
__device__ __forceinline__ void mma_bf16(float* d, const uint32_t* a, uint32_t b0, uint32_t b1) {
    asm volatile(
        "mma.sync.aligned.m16n8k16.row.col.f32.bf16.bf16.f32 "
        "{%0,%1,%2,%3}, {%4,%5,%6,%7}, {%8,%9}, {%0,%1,%2,%3};"
        : "+f"(d[0]), "+f"(d[1]), "+f"(d[2]), "+f"(d[3])
        : "r"(a[0]), "r"(a[1]), "r"(a[2]), "r"(a[3]), "r"(b0), "r"(b1));
}

// ================= split-pack (vectorized, row-ranged) =================
// mode 0 (A): [hi | lo | hi]; mode 1 (B): [hi | hi | lo]; rows >= srcRows -> zeros
__global__ void pack_split(const float* __restrict__ src, __nv_bfloat16* __restrict__ dst,
                           int srcRows, int rowStart, int rowEnd, int K, int mode) {
    const int K8 = K >> 3;
    const size_t total = (size_t)(rowEnd - rowStart) * K8;
    for (size_t v = (size_t)blockIdx.x * 256 + threadIdx.x; v < total;
         v += (size_t)gridDim.x * 256) {
        const int r = rowStart + (int)(v / K8);
        const int k = (int)(v % K8) << 3;
        float x[8];
        if (r < srcRows) {
            const float4 f0 = *(const float4*)(src + (size_t)r * K + k);
            const float4 f1 = *(const float4*)(src + (size_t)r * K + k + 4);
            x[0] = f0.x; x[1] = f0.y; x[2] = f0.z; x[3] = f0.w;
            x[4] = f1.x; x[5] = f1.y; x[6] = f1.z; x[7] = f1.w;
        } else {
#pragma unroll
            for (int i = 0; i < 8; i++) x[i] = 0.f;
        }
        union { __nv_bfloat16 h[8]; uint4 u; } uh, ul;
#pragma unroll
        for (int i = 0; i < 8; i++) {
            uh.h[i] = __float2bfloat16(x[i]);
            ul.h[i] = __float2bfloat16(x[i] - __bfloat162float(uh.h[i]));
        }
        const size_t ro = (size_t)r * 3 * K + k;
        *(uint4*)(dst + ro) = uh.u;
        if (mode == 0) {
            *(uint4*)(dst + ro + K) = ul.u;
            *(uint4*)(dst + ro + 2 * K) = uh.u;
        } else {
            *(uint4*)(dst + ro + K) = uh.u;
            *(uint4*)(dst + ro + 2 * K) = ul.u;
        }
    }
}

// ================= HMMA GEMM: C[M,N] = A[M,K3] * B[N,K3]^T =================
// bf16 in, fp32 accum. CTA 128x128, BK=64, 3-stage cp.async pipeline, 2 CTAs/SM.
#define GSTAGES 3
#define GSTAGE_BYTES 32768          // A 16KB + B 16KB
#define GEMM_DYN_SMEM (GSTAGES * GSTAGE_BYTES)

__device__ __forceinline__ void gemm_load_stage(
    const __nv_bfloat16* __restrict__ A, const __nv_bfloat16* __restrict__ B,
    int K3, int m0, int n0, int tid, uint32_t sb, int stage, int kk) {
    const uint32_t abase = sb + stage * GSTAGE_BYTES;
    const uint32_t bbase = abase + 16384;
    const int k0 = kk * 64;
#pragma unroll
    for (int it = 0; it < 4; it++) {
        const int idx = it * 256 + tid;          // 0..1023
        const int row = idx >> 3;
        const int ch = idx & 7;
        const int csw = ch ^ (row & 7);
        cp_async16(abase + row * 128 + csw * 16,
                   A + (size_t)(m0 + row) * K3 + k0 + ch * 8);
    }
#pragma unroll
    for (int it = 0; it < 4; it++) {
        const int idx = it * 256 + tid;
        const int row = idx >> 3;
        const int ch = idx & 7;
        const int csw = ch ^ (row & 7);
        cp_async16(bbase + row * 128 + csw * 16,
                   B + (size_t)(n0 + row) * K3 + k0 + ch * 8);
    }
}

__global__ __launch_bounds__(256, 2)
void tgemm(const __nv_bfloat16* __restrict__ A, const __nv_bfloat16* __restrict__ B,
           float* __restrict__ C, int K3, int Nvalid, int Nstride) {
    extern __shared__ char dynsm[];
    const uint32_t sb = smem_u32(dynsm);
    const int tid = threadIdx.x;
    const int lane = tid & 31;
    const int wid = tid >> 5;
    const int wm = wid & 3;
    const int wn = wid >> 2;

    // CTA swizzle: groups of 16 M-blocks iterate over all N (L2-friendly)
    const int gridM = gridDim.x;
    const int gridN = gridDim.y;
    const int bid = blockIdx.y * gridM + blockIdx.x;
    const int GM = 16;
    const int group = bid / (GM * gridN);
    const int rem = bid - group * (GM * gridN);
    const int m0 = (group * GM + (rem % GM)) * 128;
    const int n0 = (rem / GM) * 128;
    const int nK = K3 >> 6;

    float acc[2][8][4];
#pragma unroll
    for (int i = 0; i < 2; i++)
#pragma unroll
        for (int j = 0; j < 8; j++)
#pragma unroll
            for (int q = 0; q < 4; q++) acc[i][j][q] = 0.f;

    gemm_load_stage(A, B, K3, m0, n0, tid, sb, 0, 0); CP_COMMIT();
    gemm_load_stage(A, B, K3, m0, n0, tid, sb, 1, 1); CP_COMMIT();

    const int a_row = wm * 32 + (lane & 15);
    const int a_chg = lane >> 4;
    const int b_g = lane >> 3;
    const int b_row = wn * 64 + ((b_g >> 1) << 3) + (lane & 7);
    const int b_chg = b_g & 1;

    int buf = 0, nbuf = 2;
    for (int i = 0; i < nK; i++) {
        asm volatile("cp.async.wait_group 1;" ::: "memory");
        __syncthreads();
        if (i + 2 < nK) gemm_load_stage(A, B, K3, m0, n0, tid, sb, nbuf, i + 2);
        CP_COMMIT();

        const uint32_t abase = sb + buf * GSTAGE_BYTES;
        const uint32_t bbase = abase + 16384;
#pragma unroll
        for (int kk = 0; kk < 4; kk++) {
            uint32_t af[2][4];
#pragma unroll
            for (int mi = 0; mi < 2; mi++) {
                const int row = a_row + mi * 16;
                const int ch = kk * 2 + a_chg;
                const int csw = ch ^ (row & 7);
                ldsm_x4(abase + row * 128 + csw * 16,
                        af[mi][0], af[mi][1], af[mi][2], af[mi][3]);
            }
            uint32_t bf[4][4];
#pragma unroll
            for (int nb = 0; nb < 4; nb++) {
                const int row = b_row + nb * 16;
                const int ch = kk * 2 + b_chg;
                const int csw = ch ^ (row & 7);
                ldsm_x4(bbase + row * 128 + csw * 16,
                        bf[nb][0], bf[nb][1], bf[nb][2], bf[nb][3]);
            }
#pragma unroll
            for (int mi = 0; mi < 2; mi++)
#pragma unroll
                for (int nb = 0; nb < 4; nb++) {
                    mma_bf16(acc[mi][nb * 2 + 0], af[mi], bf[nb][0], bf[nb][1]);
                    mma_bf16(acc[mi][nb * 2 + 1], af[mi], bf[nb][2], bf[nb][3]);
                }
        }
        __syncthreads();
        buf = (buf + 1 == GSTAGES) ? 0 : buf + 1;
        nbuf = (nbuf + 1 == GSTAGES) ? 0 : nbuf + 1;
    }

    const int erow = (lane >> 2);
    const int ecol = (lane & 3) << 1;
#pragma unroll
    for (int mi = 0; mi < 2; mi++) {
        const int r = m0 + wm * 32 + mi * 16 + erow;
#pragma unroll
        for (int f = 0; f < 8; f++) {
            const int c = n0 + wn * 64 + (f >> 1) * 16 + (f & 1) * 8 + ecol;
            if (c < Nvalid) {
                *(float2*)(C + (size_t)r * Nstride + c) =
                    make_float2(acc[mi][f][0], acc[mi][f][1]);
                *(float2*)(C + (size_t)(r + 8) * Nstride + c) =
                    make_float2(acc[mi][f][2], acc[mi][f][3]);
            }
        }
    }
}

// ---------------- depthwise causal conv (K=4) + bias + silu, 4 t/thread ----------------
__global__ void conv_silu_kernel(const float* __restrict__ cw, const float* __restrict__ cb) {
    const int c = blockIdx.x * 256 + threadIdx.x;
    const int tb = blockIdx.y * 4;
    const float w0 = cw[c * 4 + 0], w1 = cw[c * 4 + 1],
                w2 = cw[c * 4 + 2], w3 = cw[c * 4 + 3];
    const float bias = cb[c];
    float v[7];
#pragma unroll
    for (int k = 0; k < 7; k++) {
        const int tt = tb - 3 + k;
        v[k] = (tt >= 0) ? g_proj[(size_t)tt * PROJD + INTERD + c] : 0.f;
    }
#pragma unroll
    for (int j = 0; j < 4; j++) {
        const float a = bias + v[j] * w0 + v[j + 1] * w1 + v[j + 2] * w2 + v[j + 3] * w3;
        g_hconv[(size_t)(tb + j) * CONVD + c] = a / (1.f + __expf(-a));
    }
}

// ---------------- fused softplus(dt)+cumsum per (chunk, head) ----------------
__global__ void dtacum_kernel(const float* __restrict__ dt_bias,
                              const float* __restrict__ A_log) {
    const int chunk = blockIdx.x;
    const int h = blockIdx.y;
    const int tid = threadIdx.x;
    const float Ah = -expf(A_log[h]);
    const float bias = dt_bias[h];
    __shared__ float s[CSZ];
    const int t = chunk * CSZ + tid;
    const float x = g_proj[(size_t)t * PROJD + DTOFF + h] + bias;
    const float dt2 = (x > 20.f) ? x : log1pf(expf(x));
    g_dt2[t * NH + h] = dt2;
    s[tid] = Ah * dt2;
    for (int off = 1; off < CSZ; off <<= 1) {
        __syncthreads();
        const float v = (tid >= off) ? s[tid - off] : 0.f;
        __syncthreads();
        s[tid] += v;
    }
    g_acum[h * SS + t] = s[tid];
}

// ---------------- fused SSD per (chunk, head) ----------------
#define SSD_SMEM_FLOATS (8320 + 4096 + 4112 + 16640 + 256)
__global__ __launch_bounds__(256, 1)
void ssd_kernel(const float* __restrict__ Dp) {
    extern __shared__ float sm[];
    float* Bts = sm;                         // [128][65]
    float* Xt  = sm + 8320;                  // [64][64]
    float* Cs  = sm + 8320 + 4096;           // [16][257]
    float* Gw  = sm + 8320 + 4096 + 4112;    // [256][65]
    float* acs = Gw + 16640;                 // [256]

    const int tid = threadIdx.x;
    const int chunk = blockIdx.x;
    const int h = blockIdx.y;
    const int t0 = chunk * CSZ;
    const int grp = h & 7;
    const int Bbase = INTERD + grp * SN;
    const int Cbase = INTERD + NG * SN + grp * SN;
    const int tx = tid & 15, ty = tid >> 4;

    acs[tid] = g_acum[h * SS + t0 + tid];
    __syncthreads();
    const float alast = acs[CSZ - 1];

    float yacc[64];
#pragma unroll
    for (int p = 0; p < 64; p++) yacc[p] = 0.f;

    for (int jt = 0; jt < 4; ++jt) {
        const int jbase = jt * 64;
#pragma unroll
        for (int it = 0; it < 8; ++it) {
            const int idx = it * 256 + tid;
            const int jj = idx >> 5;
            const int n4 = (idx & 31) << 2;
            const float4 v = *(const float4*)(g_hconv + (size_t)(t0 + jbase + jj) * CONVD + Bbase + n4);
            Bts[(n4 + 0) * 65 + jj] = v.x; Bts[(n4 + 1) * 65 + jj] = v.y;
            Bts[(n4 + 2) * 65 + jj] = v.z; Bts[(n4 + 3) * 65 + jj] = v.w;
        }
#pragma unroll
        for (int it = 0; it < 4; ++it) {
            const int idx = it * 256 + tid;
            const int jj = idx >> 4;
            const int p4 = (idx & 15) << 2;
            const int tj = t0 + jbase + jj;
            float4 v = *(const float4*)(g_hconv + (size_t)tj * CONVD + h * HP + p4);
            const float sc = g_dt2[tj * NH + h];
            v.x *= sc; v.y *= sc; v.z *= sc; v.w *= sc;
            *(float4*)(Xt + jj * 64 + p4) = v;
        }
        __syncthreads();

        float gacc[64];
#pragma unroll
        for (int q = 0; q < 64; q++) gacc[q] = 0.f;
        for (int n0 = 0; n0 < SN; n0 += 16) {
#pragma unroll
            for (int it = 0; it < 16; ++it) {
                const int idx = it * 256 + tid;
                const int i = idx >> 4;
                const int nn = idx & 15;
                Cs[nn * 257 + i] = g_hconv[(size_t)(t0 + i) * CONVD + Cbase + n0 + nn];
            }
            __syncthreads();
#pragma unroll
            for (int kk = 0; kk < 16; kk++) {
                float a[16];
#pragma unroll
                for (int u = 0; u < 16; u++) a[u] = Cs[kk * 257 + ty * 16 + u];
                const float* br = Bts + (n0 + kk) * 65 + tx * 4;
                const float b0 = br[0], b1 = br[1], b2 = br[2], b3 = br[3];
#pragma unroll
                for (int u = 0; u < 16; u++) {
                    gacc[u * 4 + 0] += a[u] * b0;
                    gacc[u * 4 + 1] += a[u] * b1;
                    gacc[u * 4 + 2] += a[u] * b2;
                    gacc[u * 4 + 3] += a[u] * b3;
                }
            }
            __syncthreads();
        }
#pragma unroll
        for (int u = 0; u < 16; u++) {
            const int i = ty * 16 + u;
            const float ai = acs[i];
#pragma unroll
            for (int v = 0; v < 4; v++) {
                const int j = tx * 4 + v;
                const int jg = jbase + j;
                const float d = ai - acs[jg];
                float w = __expf(d + alast);
                if (jg <= i) w += __expf(d);
                Gw[i * 65 + j] = gacc[u * 4 + v] * w;
            }
        }
        __syncthreads();
#pragma unroll 4
        for (int j = 0; j < 64; j++) {
            const float gv = Gw[tid * 65 + j];
            const float4* xr = (const float4*)(Xt + (j << 6));
#pragma unroll
            for (int p4 = 0; p4 < 16; p4++) {
                const float4 xv = xr[p4];
                yacc[p4 * 4 + 0] += gv * xv.x;
                yacc[p4 * 4 + 1] += gv * xv.y;
                yacc[p4 * 4 + 2] += gv * xv.z;
                yacc[p4 * 4 + 3] += gv * xv.w;
            }
        }
        __syncthreads();
    }

    const float Dh = Dp[h];
    const float4* hrow = (const float4*)(g_hconv + (size_t)(t0 + tid) * CONVD + h * HP);
#pragma unroll
    for (int p4 = 0; p4 < 16; p4++) {
        const float4 hv = hrow[p4];
        yacc[p4 * 4 + 0] += Dh * hv.x;
        yacc[p4 * 4 + 1] += Dh * hv.y;
        yacc[p4 * 4 + 2] += Dh * hv.z;
        yacc[p4 * 4 + 3] += Dh * hv.w;
    }
#pragma unroll
    for (int p = 0; p < 64; p++) Gw[tid * 65 + p] = yacc[p];
    __syncthreads();
#pragma unroll
    for (int it = 0; it < 16; ++it) {
        const int idx = it * 256 + tid;
        const int i = idx >> 4;
        const int p4 = (idx & 15) << 2;
        float4 v;
        v.x = Gw[i * 65 + p4 + 0]; v.y = Gw[i * 65 + p4 + 1];
        v.z = Gw[i * 65 + p4 + 2]; v.w = Gw[i * 65 + p4 + 3];
        *(float4*)(g_y + (size_t)(t0 + i) * INTERD + h * HP + p4) = v;
    }
}

// ---------------- gate silu + RMSNorm + split-bf16 A-pack (fused) ----------------
__global__ void norm_pack_kernel(const float* __restrict__ norm_w) {
    const int t = blockIdx.x;
    const int tid = threadIdx.x;
    __shared__ float red[256];
    __shared__ float yg_s[INTERD];
    float local = 0.f;
    for (int c = tid; c < INTERD; c += 256) {
        const float g = g_proj[(size_t)t * PROJD + c];
        const float yv = g_y[(size_t)t * INTERD + c];
        const float yg = yv * (g / (1.f + __expf(-g)));
        yg_s[c] = yg;
        local += yg * yg;
    }
    red[tid] = local;
    __syncthreads();
    for (int s = 128; s > 0; s >>= 1) {
        if (tid < s) red[tid] += red[tid + s];
        __syncthreads();
    }
    const float rstd = rsqrtf(red[0] / (float)INTERD + 1e-6f);
    __nv_bfloat16* dst = g_Apack + (size_t)t * 3 * INTERD;
    for (int c = tid * 4; c < INTERD; c += 1024) {
        union { __nv_bfloat16 h[4]; uint2 u; } uh, ul;
#pragma unroll
        for (int i = 0; i < 4; i++) {
            const float v = norm_w[c + i] * yg_s[c + i] * rstd;
            uh.h[i] = __float2bfloat16(v);
            ul.h[i] = __float2bfloat16(v - __bfloat162float(uh.h[i]));
        }
        *(uint2*)(dst + c) = uh.u;
        *(uint2*)(dst + INTERD + c) = ul.u;
        *(uint2*)(dst + 2 * INTERD + c) = uh.u;
    }
}

// ---------------- launch ----------------
extern "C" void kernel_launch(void* const* d_in, const int* in_sizes, int n_in,
                              void* d_out, int out_size) {
    (void)in_sizes; (void)n_in; (void)out_size;
    const float* x       = (const float*)d_in[0];
    const float* w_in    = (const float*)d_in[1];
    const float* conv_w  = (const float*)d_in[2];
    const float* conv_b  = (const float*)d_in[3];
    const float* dt_bias = (const float*)d_in[4];
    const float* A_log   = (const float*)d_in[5];
    const float* Dv      = (const float*)d_in[6];
    const float* norm_w  = (const float*)d_in[7];
    const float* w_out   = (const float*)d_in[8];
    float* out = (float*)d_out;

    float* p_proj = nullptr;
    __nv_bfloat16* p_Apack = nullptr;
    __nv_bfloat16* p_B1 = nullptr;
    __nv_bfloat16* p_B2 = nullptr;
    cudaGetSymbolAddress((void**)&p_proj, g_proj);
    cudaGetSymbolAddress((void**)&p_Apack, g_Apack);
    cudaGetSymbolAddress((void**)&p_B1, g_B1);
    cudaGetSymbolAddress((void**)&p_B2, g_B2);

    cudaFuncSetAttribute(tgemm, cudaFuncAttributeMaxDynamicSharedMemorySize, GEMM_DYN_SMEM);
    cudaFuncSetAttribute(ssd_kernel, cudaFuncAttributeMaxDynamicSharedMemorySize,
                         SSD_SMEM_FLOATS * (int)sizeof(float));

    // --- GEMM1 packs (B pack split into 2 so tgemm is the 4th launch for ncu) ---
    pack_split<<<2048, 256>>>(x, p_Apack, SS, 0, SS, EMB, 0);
    pack_split<<<2048, 256>>>(w_in, p_B1, PROJD, 0, PROJPAD / 2, EMB, 1);
    pack_split<<<2048, 256>>>(w_in, p_B1, PROJD, PROJPAD / 2, PROJPAD, EMB, 1);
    // --- GEMM1: proj = X @ W_in^T ---
    tgemm<<<dim3(SS / 128, PROJPAD / 128), 256, GEMM_DYN_SMEM>>>(
        p_Apack, p_B1, p_proj, 3 * EMB, PROJD, PROJD);

    // --- elementwise / scan stages ---
    conv_silu_kernel<<<dim3(CONVD / 256, SS / 4), 256>>>(conv_w, conv_b);
    dtacum_kernel<<<dim3(NCH, NH), CSZ>>>(dt_bias, A_log);
    ssd_kernel<<<dim3(NCH, NH), 256, SSD_SMEM_FLOATS * (int)sizeof(float)>>>(Dv);
    norm_pack_kernel<<<SS, 256>>>(norm_w);

    // --- GEMM2: out = normed @ W_out^T ---
    pack_split<<<2048, 256>>>(w_out, p_B2, EMB, 0, EMB, INTERD, 1);
    tgemm<<<dim3(SS / 128, EMB / 128), 256, GEMM_DYN_SMEM>>>(
        p_Apack, p_B2, out, 3 * INTERD, EMB, EMB);
}

// round 6
// speedup vs baseline: 5.1835x; 1.1924x over previous
#include <cuda_runtime.h>
#include <cuda_bf16.h>
#include <cstdint>
#include <cstddef>

// ---------------- problem constants ----------------
#define SS      4096
#define EMB     2048
#define PROJD   10304
#define PROJPAD 10368
#define INTERD  4096
#define CONVD   6144
#define NH      64
#define HP      64
#define SN      128
#define NG      8
#define CSZ     256
#define NCH     16
#define DTOFF   10240

// ---------------- scratch ----------------
__device__ float g_proj[(size_t)SS * PROJD];
__device__ float g_hconv[(size_t)SS * CONVD];
__device__ float g_dt2[SS * NH];
__device__ float g_acum[NH * SS];
__device__ float g_y[(size_t)SS * INTERD];
__device__ __nv_bfloat16 g_Apack[(size_t)SS * 3 * INTERD];
__device__ __nv_bfloat16 g_B1[(size_t)PROJPAD * 3 * EMB];
__device__ __nv_bfloat16 g_B2[(size_t)EMB * 3 * INTERD];

// ================= helpers =================
__device__ __forceinline__ uint32_t smem_u32(const void* p) {
    uint32_t a;
    asm("{ .reg .u64 t; cvta.to.shared.u64 t, %1; cvt.u32.u64 %0, t; }" : "=r"(a) : "l"(p));
    return a;
}
__device__ __forceinline__ void cp_async16(uint32_t saddr, const void* g) {
    asm volatile("cp.async.cg.shared.global [%0], [%1], 16;" :: "r"(saddr), "l"(g) : "memory");
}
#define CP_COMMIT() asm volatile("cp.async.commit_group;" ::: "memory")

__device__ __forceinline__ void ldsm_x4(uint32_t addr, uint32_t& r0, uint32_t& r1,
                                        uint32_t& r2, uint32_t& r3) {
    asm volatile("ldmatrix.sync.aligned.m8n8.x4.shared.b16 {%0,%1,%2,%3}, [%4];"
                 : "=r"(r0), "=r"(r1), "=r"(r2), "=r"(r3) : "r"(addr));
}
__device__ __forceinline__ void mma_bf16(float* d, const uint32_t* a, uint32_t b0, uint32_t b1) {
    asm volatile(
        "mma.sync.aligned.m16n8k16.row.col.f32.bf16.bf16.f32 "
        "{%0,%1,%2,%3}, {%4,%5,%6,%7}, {%8,%9}, {%0,%1,%2,%3};"
        : "+f"(d[0]), "+f"(d[1]), "+f"(d[2]), "+f"(d[3])
        : "r"(a[0]), "r"(a[1]), "r"(a[2]), "r"(a[3]), "r"(b0), "r"(b1));
}
__device__ __forceinline__ uint32_t pack_bf2(float x, float y) {
    __nv_bfloat16 a = __float2bfloat16(x);
    __nv_bfloat16 b = __float2bfloat16(y);
    return (uint32_t)__bfloat16_as_ushort(a) | ((uint32_t)__bfloat16_as_ushort(b) << 16);
}

// ================= split-pack (vectorized, row-ranged) =================
__global__ void pack_split(const float* __restrict__ src, __nv_bfloat16* __restrict__ dst,
                           int srcRows, int rowStart, int rowEnd, int K, int mode) {
    const int K8 = K >> 3;
    const size_t total = (size_t)(rowEnd - rowStart) * K8;
    for (size_t v = (size_t)blockIdx.x * 256 + threadIdx.x; v < total;
         v += (size_t)gridDim.x * 256) {
        const int r = rowStart + (int)(v / K8);
        const int k = (int)(v % K8) << 3;
        float x[8];
        if (r < srcRows) {
            const float4 f0 = *(const float4*)(src + (size_t)r * K + k);
            const float4 f1 = *(const float4*)(src + (size_t)r * K + k + 4);
            x[0] = f0.x; x[1] = f0.y; x[2] = f0.z; x[3] = f0.w;
            x[4] = f1.x; x[5] = f1.y; x[6] = f1.z; x[7] = f1.w;
        } else {
#pragma unroll
            for (int i = 0; i < 8; i++) x[i] = 0.f;
        }
        union { __nv_bfloat16 h[8]; uint4 u; } uh, ul;
#pragma unroll
        for (int i = 0; i < 8; i++) {
            uh.h[i] = __float2bfloat16(x[i]);
            ul.h[i] = __float2bfloat16(x[i] - __bfloat162float(uh.h[i]));
        }
        const size_t ro = (size_t)r * 3 * K + k;
        *(uint4*)(dst + ro) = uh.u;
        if (mode == 0) {
            *(uint4*)(dst + ro + K) = ul.u;
            *(uint4*)(dst + ro + 2 * K) = uh.u;
        } else {
            *(uint4*)(dst + ro + K) = uh.u;
            *(uint4*)(dst + ro + 2 * K) = ul.u;
        }
    }
}

// ================= HMMA GEMM: C[M,N] = A[M,K3] * B[N,K3]^T =================
#define GSTAGES 3
#define GSTAGE_BYTES 32768
#define GEMM_DYN_SMEM (GSTAGES * GSTAGE_BYTES)

__device__ __forceinline__ void gemm_load_stage(
    const __nv_bfloat16* __restrict__ A, const __nv_bfloat16* __restrict__ B,
    int K3, int m0, int n0, int tid, uint32_t sb, int stage, int kk) {
    const uint32_t abase = sb + stage * GSTAGE_BYTES;
    const uint32_t bbase = abase + 16384;
    const int k0 = kk * 64;
#pragma unroll
    for (int it = 0; it < 4; it++) {
        const int idx = it * 256 + tid;
        const int row = idx >> 3;
        const int ch = idx & 7;
        const int csw = ch ^ (row & 7);
        cp_async16(abase + row * 128 + csw * 16,
                   A + (size_t)(m0 + row) * K3 + k0 + ch * 8);
    }
#pragma unroll
    for (int it = 0; it < 4; it++) {
        const int idx = it * 256 + tid;
        const int row = idx >> 3;
        const int ch = idx & 7;
        const int csw = ch ^ (row & 7);
        cp_async16(bbase + row * 128 + csw * 16,
                   B + (size_t)(n0 + row) * K3 + k0 + ch * 8);
    }
}

__global__ __launch_bounds__(256, 2)
void tgemm(const __nv_bfloat16* __restrict__ A, const __nv_bfloat16* __restrict__ B,
           float* __restrict__ C, int K3, int Nvalid, int Nstride) {
    extern __shared__ char dynsm[];
    const uint32_t sb = smem_u32(dynsm);
    const int tid = threadIdx.x;
    const int lane = tid & 31;
    const int wid = tid >> 5;
    const int wm = wid & 3;
    const int wn = wid >> 2;

    const int gridM = gridDim.x;
    const int gridN = gridDim.y;
    const int bid = blockIdx.y * gridM + blockIdx.x;
    const int GM = 16;
    const int group = bid / (GM * gridN);
    const int rem = bid - group * (GM * gridN);
    const int m0 = (group * GM + (rem % GM)) * 128;
    const int n0 = (rem / GM) * 128;
    const int nK = K3 >> 6;

    float acc[2][8][4];
#pragma unroll
    for (int i = 0; i < 2; i++)
#pragma unroll
        for (int j = 0; j < 8; j++)
#pragma unroll
            for (int q = 0; q < 4; q++) acc[i][j][q] = 0.f;

    gemm_load_stage(A, B, K3, m0, n0, tid, sb, 0, 0); CP_COMMIT();
    gemm_load_stage(A, B, K3, m0, n0, tid, sb, 1, 1); CP_COMMIT();

    const int a_row = wm * 32 + (lane & 15);
    const int a_chg = lane >> 4;
    const int b_g = lane >> 3;
    const int b_row = wn * 64 + ((b_g >> 1) << 3) + (lane & 7);
    const int b_chg = b_g & 1;

    int buf = 0, nbuf = 2;
    for (int i = 0; i < nK; i++) {
        asm volatile("cp.async.wait_group 1;" ::: "memory");
        __syncthreads();
        if (i + 2 < nK) gemm_load_stage(A, B, K3, m0, n0, tid, sb, nbuf, i + 2);
        CP_COMMIT();

        const uint32_t abase = sb + buf * GSTAGE_BYTES;
        const uint32_t bbase = abase + 16384;
#pragma unroll
        for (int kk = 0; kk < 4; kk++) {
            uint32_t af[2][4];
#pragma unroll
            for (int mi = 0; mi < 2; mi++) {
                const int row = a_row + mi * 16;
                const int ch = kk * 2 + a_chg;
                const int csw = ch ^ (row & 7);
                ldsm_x4(abase + row * 128 + csw * 16,
                        af[mi][0], af[mi][1], af[mi][2], af[mi][3]);
            }
            uint32_t bf[4][4];
#pragma unroll
            for (int nb = 0; nb < 4; nb++) {
                const int row = b_row + nb * 16;
                const int ch = kk * 2 + b_chg;
                const int csw = ch ^ (row & 7);
                ldsm_x4(bbase + row * 128 + csw * 16,
                        bf[nb][0], bf[nb][1], bf[nb][2], bf[nb][3]);
            }
#pragma unroll
            for (int mi = 0; mi < 2; mi++)
#pragma unroll
                for (int nb = 0; nb < 4; nb++) {
                    mma_bf16(acc[mi][nb * 2 + 0], af[mi], bf[nb][0], bf[nb][1]);
                    mma_bf16(acc[mi][nb * 2 + 1], af[mi], bf[nb][2], bf[nb][3]);
                }
        }
        // NOTE: no trailing __syncthreads needed — the top-of-loop barrier of the
        // next iteration orders this iteration's ldsm reads before the next loads.
        buf = (buf + 1 == GSTAGES) ? 0 : buf + 1;
        nbuf = (nbuf + 1 == GSTAGES) ? 0 : nbuf + 1;
    }

    const int erow = (lane >> 2);
    const int ecol = (lane & 3) << 1;
#pragma unroll
    for (int mi = 0; mi < 2; mi++) {
        const int r = m0 + wm * 32 + mi * 16 + erow;
#pragma unroll
        for (int f = 0; f < 8; f++) {
            const int c = n0 + wn * 64 + (f >> 1) * 16 + (f & 1) * 8 + ecol;
            if (c < Nvalid) {
                *(float2*)(C + (size_t)r * Nstride + c) =
                    make_float2(acc[mi][f][0], acc[mi][f][1]);
                *(float2*)(C + (size_t)(r + 8) * Nstride + c) =
                    make_float2(acc[mi][f][2], acc[mi][f][3]);
            }
        }
    }
}

// ---------------- depthwise causal conv (K=4) + bias + silu, 4 t/thread ----------------
__global__ void conv_silu_kernel(const float* __restrict__ cw, const float* __restrict__ cb) {
    const int c = blockIdx.x * 256 + threadIdx.x;
    const int tb = blockIdx.y * 4;
    const float w0 = cw[c * 4 + 0], w1 = cw[c * 4 + 1],
                w2 = cw[c * 4 + 2], w3 = cw[c * 4 + 3];
    const float bias = cb[c];
    float v[7];
#pragma unroll
    for (int k = 0; k < 7; k++) {
        const int tt = tb - 3 + k;
        v[k] = (tt >= 0) ? g_proj[(size_t)tt * PROJD + INTERD + c] : 0.f;
    }
#pragma unroll
    for (int j = 0; j < 4; j++) {
        const float a = bias + v[j] * w0 + v[j + 1] * w1 + v[j + 2] * w2 + v[j + 3] * w3;
        g_hconv[(size_t)(tb + j) * CONVD + c] = a / (1.f + __expf(-a));
    }
}

// ---------------- fused softplus(dt)+cumsum per (chunk, head) ----------------
__global__ void dtacum_kernel(const float* __restrict__ dt_bias,
                              const float* __restrict__ A_log) {
    const int chunk = blockIdx.x;
    const int h = blockIdx.y;
    const int tid = threadIdx.x;
    const float Ah = -expf(A_log[h]);
    const float bias = dt_bias[h];
    __shared__ float s[CSZ];
    const int t = chunk * CSZ + tid;
    const float x = g_proj[(size_t)t * PROJD + DTOFF + h] + bias;
    const float dt2 = (x > 20.f) ? x : log1pf(expf(x));
    g_dt2[t * NH + h] = dt2;
    s[tid] = Ah * dt2;
    for (int off = 1; off < CSZ; off <<= 1) {
        __syncthreads();
        const float v = (tid >= off) ? s[tid - off] : 0.f;
        __syncthreads();
        s[tid] += v;
    }
    g_acum[h * SS + t] = s[tid];
}

// ================= SSD via HMMA (split-bf16 3-term) =================
// Per (chunk, head):
//   stage1: Gm[i,j] = C_i . B_j over n=128  (HMMA, 3 terms)
//   weight: Gw = Gm * (exp(ai-aj+alast) + [j<=i] exp(ai-aj))   (in fragments)
//   stage2: Y[i,p] += Gw[i,j] @ X[j,p] over j=64 per tile (HMMA, 3 terms)
// smem: Chi/Clo 256x128 bf16 (64KB each); per-jt: Bhi/Blo 64x128 (16KB each,
// overlapping the Gw-hi region), Gw hi/lo 256x64 (32KB each), X hi/lo transposed
// [p][j] 64x64 (8KB each), acs 1KB. Total 214016 B.
#define S_CHI 0
#define S_CLO 65536
#define S_GWH 131072
#define S_BHI 131072
#define S_BLO 147456
#define S_GWL 163840
#define S_XHI 196608
#define S_XLO 204800
#define S_ACS 212992
#define SSD_DYN_SMEM (S_ACS + 1024)

__global__ __launch_bounds__(256, 1)
void ssd_hmma(const float* __restrict__ Dp) {
    extern __shared__ char sm[];
    const uint32_t sb = smem_u32(sm);
    float* acs = (float*)(sm + S_ACS);
    const int tid = threadIdx.x;
    const int lane = tid & 31;
    const int w = tid >> 5;
    const int chunk = blockIdx.x;
    const int h = blockIdx.y;
    const int t0 = chunk * CSZ;
    const int grp = h & 7;
    const int Bbase = INTERD + grp * SN;
    const int Cbase = INTERD + NG * SN + grp * SN;
    const int i0 = w * 32;

    acs[tid] = g_acum[h * SS + t0 + tid];

    // load + split C: 256 rows x 128 n (rows of 256B in smem, 16 chunks, swizzled)
#pragma unroll 4
    for (int it = 0; it < 16; it++) {
        const int u = it * 256 + tid;
        const int i = u >> 4;
        const int nb = u & 15;
        const float* src = g_hconv + (size_t)(t0 + i) * CONVD + Cbase + nb * 8;
        const float4 f0 = *(const float4*)(src);
        const float4 f1 = *(const float4*)(src + 4);
        const float xv[8] = {f0.x, f0.y, f0.z, f0.w, f1.x, f1.y, f1.z, f1.w};
        union { __nv_bfloat16 b[8]; uint4 u4; } hh, ll;
#pragma unroll
        for (int q = 0; q < 8; q++) {
            hh.b[q] = __float2bfloat16(xv[q]);
            ll.b[q] = __float2bfloat16(xv[q] - __bfloat162float(hh.b[q]));
        }
        const int csw = nb ^ (i & 7);
        *(uint4*)(sm + S_CHI + i * 256 + csw * 16) = hh.u4;
        *(uint4*)(sm + S_CLO + i * 256 + csw * 16) = ll.u4;
    }
    __syncthreads();
    const float alast = acs[CSZ - 1];
    const int ro = lane >> 2;
    const int co = (lane & 3) * 2;

    float yacc[2][8][4];
#pragma unroll
    for (int mi = 0; mi < 2; mi++)
#pragma unroll
        for (int nb = 0; nb < 8; nb++)
#pragma unroll
            for (int q = 0; q < 4; q++) yacc[mi][nb][q] = 0.f;

    for (int jt = 0; jt < 4; jt++) {
        const int jb = jt * 64;
        // load + split B tile: 64 rows x 128 n
#pragma unroll
        for (int it = 0; it < 4; it++) {
            const int u = it * 256 + tid;
            const int j = u >> 4;
            const int nb = u & 15;
            const float* src = g_hconv + (size_t)(t0 + jb + j) * CONVD + Bbase + nb * 8;
            const float4 f0 = *(const float4*)(src);
            const float4 f1 = *(const float4*)(src + 4);
            const float xv[8] = {f0.x, f0.y, f0.z, f0.w, f1.x, f1.y, f1.z, f1.w};
            union { __nv_bfloat16 b[8]; uint4 u4; } hh, ll;
#pragma unroll
            for (int q = 0; q < 8; q++) {
                hh.b[q] = __float2bfloat16(xv[q]);
                ll.b[q] = __float2bfloat16(xv[q] - __bfloat162float(hh.b[q]));
            }
            const int csw = nb ^ (j & 7);
            *(uint4*)(sm + S_BHI + j * 256 + csw * 16) = hh.u4;
            *(uint4*)(sm + S_BLO + j * 256 + csw * 16) = ll.u4;
        }
        // load + split X (hid*dt2), store TRANSPOSED [p][j] (rows 128B, swizzled)
#pragma unroll
        for (int it = 0; it < 4; it++) {
            const int u = it * 256 + tid;
            const int j = u >> 4;
            const int pb = (u & 15) * 4;
            const int tj = t0 + jb + j;
            float4 v = *(const float4*)(g_hconv + (size_t)tj * CONVD + h * HP + pb);
            const float sc = g_dt2[tj * NH + h];
            const float xv[4] = {v.x * sc, v.y * sc, v.z * sc, v.w * sc};
            const int wo = (j * 2) & 15;
            const int chn = j >> 3;
#pragma unroll
            for (int q = 0; q < 4; q++) {
                const int p = pb + q;
                const __nv_bfloat16 hb = __float2bfloat16(xv[q]);
                const __nv_bfloat16 lb = __float2bfloat16(xv[q] - __bfloat162float(hb));
                const uint32_t ad = p * 128 + ((chn ^ (p & 7)) << 4) + wo;
                *(__nv_bfloat16*)(sm + S_XHI + ad) = hb;
                *(__nv_bfloat16*)(sm + S_XLO + ad) = lb;
            }
        }
        __syncthreads();

        // ---- stage 1: Gram (32 i-rows per warp x 64 j), K = 128 x 3 terms ----
        float gacc[2][8][4];
#pragma unroll
        for (int mi = 0; mi < 2; mi++)
#pragma unroll
            for (int nb = 0; nb < 8; nb++)
#pragma unroll
                for (int q = 0; q < 4; q++) gacc[mi][nb][q] = 0.f;

        for (int term = 0; term < 3; term++) {
            const uint32_t Ab = sb + ((term == 1) ? S_CLO : S_CHI);
            const uint32_t Bb = sb + ((term == 2) ? S_BLO : S_BHI);
#pragma unroll
            for (int ks = 0; ks < 8; ks++) {
                uint32_t af[2][4];
#pragma unroll
                for (int mi = 0; mi < 2; mi++) {
                    const int row = i0 + mi * 16 + (lane & 15);
                    const int ch = 2 * ks + (lane >> 4);
                    const int csw = ch ^ (row & 7);
                    ldsm_x4(Ab + row * 256 + csw * 16,
                            af[mi][0], af[mi][1], af[mi][2], af[mi][3]);
                }
#pragma unroll
                for (int q = 0; q < 4; q++) {
                    const int bg = lane >> 3;
                    const int row = q * 16 + ((bg >> 1) << 3) + (lane & 7);
                    const int ch = 2 * ks + (bg & 1);
                    const int csw = ch ^ (row & 7);
                    uint32_t b0, b1, b2, b3;
                    ldsm_x4(Bb + row * 256 + csw * 16, b0, b1, b2, b3);
                    mma_bf16(gacc[0][q * 2 + 0], af[0], b0, b1);
                    mma_bf16(gacc[0][q * 2 + 1], af[0], b2, b3);
                    mma_bf16(gacc[1][q * 2 + 0], af[1], b0, b1);
                    mma_bf16(gacc[1][q * 2 + 1], af[1], b2, b3);
                }
            }
        }

        // ---- weight in-register ----
#pragma unroll
        for (int mi = 0; mi < 2; mi++) {
            const int r1 = i0 + mi * 16 + ro;
            const int r2 = r1 + 8;
            const float a1 = acs[r1];
            const float a2 = acs[r2];
#pragma unroll
            for (int nb = 0; nb < 8; nb++) {
                const int cb = (nb >> 1) * 16 + (nb & 1) * 8 + co;
                const int jg = jb + cb;
                const float aj0 = acs[jg];
                const float aj1 = acs[jg + 1];
                float wv;
                wv = __expf(a1 - aj0 + alast) + ((jg <= r1) ? __expf(a1 - aj0) : 0.f);
                gacc[mi][nb][0] *= wv;
                wv = __expf(a1 - aj1 + alast) + ((jg + 1 <= r1) ? __expf(a1 - aj1) : 0.f);
                gacc[mi][nb][1] *= wv;
                wv = __expf(a2 - aj0 + alast) + ((jg <= r2) ? __expf(a2 - aj0) : 0.f);
                gacc[mi][nb][2] *= wv;
                wv = __expf(a2 - aj1 + alast) + ((jg + 1 <= r2) ? __expf(a2 - aj1) : 0.f);
                gacc[mi][nb][3] *= wv;
            }
        }
        __syncthreads();   // all B reads complete before Gw overwrites the B region

        // ---- store Gw hi/lo to smem (rows 128B, swizzled) ----
#pragma unroll
        for (int mi = 0; mi < 2; mi++) {
            const int r1 = i0 + mi * 16 + ro;
            const int r2 = r1 + 8;
#pragma unroll
            for (int nb = 0; nb < 8; nb++) {
                const int c = (nb >> 1) * 16 + (nb & 1) * 8 + co;
                const int chn = c >> 3;
                const int wo = (c * 2) & 15;
                const uint32_t ad1 = r1 * 128 + (((chn) ^ (r1 & 7)) << 4) + wo;
                const uint32_t ad2 = r2 * 128 + (((chn) ^ (r2 & 7)) << 4) + wo;
                *(uint32_t*)(sm + S_GWH + ad1) = pack_bf2(gacc[mi][nb][0], gacc[mi][nb][1]);
                *(uint32_t*)(sm + S_GWL + ad1) = pack_bf2(
                    gacc[mi][nb][0] - __bfloat162float(__float2bfloat16(gacc[mi][nb][0])),
                    gacc[mi][nb][1] - __bfloat162float(__float2bfloat16(gacc[mi][nb][1])));
                *(uint32_t*)(sm + S_GWH + ad2) = pack_bf2(gacc[mi][nb][2], gacc[mi][nb][3]);
                *(uint32_t*)(sm + S_GWL + ad2) = pack_bf2(
                    gacc[mi][nb][2] - __bfloat162float(__float2bfloat16(gacc[mi][nb][2])),
                    gacc[mi][nb][3] - __bfloat162float(__float2bfloat16(gacc[mi][nb][3])));
            }
        }
        __syncthreads();

        // ---- stage 2: Y += Gw @ X^T, K = 64 x 3 terms ----
        for (int term = 0; term < 3; term++) {
            const uint32_t Ab = sb + ((term == 1) ? S_GWL : S_GWH);
            const uint32_t Bb = sb + ((term == 2) ? S_XLO : S_XHI);
#pragma unroll
            for (int ks = 0; ks < 4; ks++) {
                uint32_t af[2][4];
#pragma unroll
                for (int mi = 0; mi < 2; mi++) {
                    const int row = i0 + mi * 16 + (lane & 15);
                    const int ch = 2 * ks + (lane >> 4);
                    const int csw = ch ^ (row & 7);
                    ldsm_x4(Ab + row * 128 + csw * 16,
                            af[mi][0], af[mi][1], af[mi][2], af[mi][3]);
                }
#pragma unroll
                for (int q = 0; q < 4; q++) {
                    const int bg = lane >> 3;
                    const int row = q * 16 + ((bg >> 1) << 3) + (lane & 7);
                    const int ch = 2 * ks + (bg & 1);
                    const int csw = ch ^ (row & 7);
                    uint32_t b0, b1, b2, b3;
                    ldsm_x4(Bb + row * 128 + csw * 16, b0, b1, b2, b3);
                    mma_bf16(yacc[0][q * 2 + 0], af[0], b0, b1);
                    mma_bf16(yacc[0][q * 2 + 1], af[0], b2, b3);
                    mma_bf16(yacc[1][q * 2 + 0], af[1], b0, b1);
                    mma_bf16(yacc[1][q * 2 + 1], af[1], b2, b3);
                }
            }
        }
        __syncthreads();   // stage2 reads done before next jt overwrites B/X/Gw
    }

    // ---- epilogue: D residual + store Y ----
    const float Dh = Dp[h];
#pragma unroll
    for (int mi = 0; mi < 2; mi++) {
        const int r1 = t0 + i0 + mi * 16 + ro;
        const int r2 = r1 + 8;
#pragma unroll
        for (int nb = 0; nb < 8; nb++) {
            const int p = (nb >> 1) * 16 + (nb & 1) * 8 + co;
            const float2 h1 = *(const float2*)(g_hconv + (size_t)r1 * CONVD + h * HP + p);
            const float2 h2 = *(const float2*)(g_hconv + (size_t)r2 * CONVD + h * HP + p);
            *(float2*)(g_y + (size_t)r1 * INTERD + h * HP + p) =
                make_float2(yacc[mi][nb][0] + Dh * h1.x, yacc[mi][nb][1] + Dh * h1.y);
            *(float2*)(g_y + (size_t)r2 * INTERD + h * HP + p) =
                make_float2(yacc[mi][nb][2] + Dh * h2.x, yacc[mi][nb][3] + Dh * h2.y);
        }
    }
}

// ---------------- gate silu + RMSNorm + split-bf16 A-pack (fused) ----------------
__global__ void norm_pack_kernel(const float* __restrict__ norm_w) {
    const int t = blockIdx.x;
    const int tid = threadIdx.x;
    __shared__ float red[256];
    __shared__ float yg_s[INTERD];
    float local = 0.f;
    for (int c = tid; c < INTERD; c += 256) {
        const float g = g_proj[(size_t)t * PROJD + c];
        const float yv = g_y[(size_t)t * INTERD + c];
        const float yg = yv * (g / (1.f + __expf(-g)));
        yg_s[c] = yg;
        local += yg * yg;
    }
    red[tid] = local;
    __syncthreads();
    for (int s = 128; s > 0; s >>= 1) {
        if (tid < s) red[tid] += red[tid + s];
        __syncthreads();
    }
    const float rstd = rsqrtf(red[0] / (float)INTERD + 1e-6f);
    __nv_bfloat16* dst = g_Apack + (size_t)t * 3 * INTERD;
    for (int c = tid * 4; c < INTERD; c += 1024) {
        union { __nv_bfloat16 h[4]; uint2 u; } uh, ul;
#pragma unroll
        for (int i = 0; i < 4; i++) {
            const float v = norm_w[c + i] * yg_s[c + i] * rstd;
            uh.h[i] = __float2bfloat16(v);
            ul.h[i] = __float2bfloat16(v - __bfloat162float(uh.h[i]));
        }
        *(uint2*)(dst + c) = uh.u;
        *(uint2*)(dst + INTERD + c) = ul.u;
        *(uint2*)(dst + 2 * INTERD + c) = uh.u;
    }
}

// ---------------- launch ----------------
extern "C" void kernel_launch(void* const* d_in, const int* in_sizes, int n_in,
                              void* d_out, int out_size) {
    (void)in_sizes; (void)n_in; (void)out_size;
    const float* x       = (const float*)d_in[0];
    const float* w_in    = (const float*)d_in[1];
    const float* conv_w  = (const float*)d_in[2];
    const float* conv_b  = (const float*)d_in[3];
    const float* dt_bias = (const float*)d_in[4];
    const float* A_log   = (const float*)d_in[5];
    const float* Dv      = (const float*)d_in[6];
    const float* norm_w  = (const float*)d_in[7];
    const float* w_out   = (const float*)d_in[8];
    float* out = (float*)d_out;

    float* p_proj = nullptr;
    __nv_bfloat16* p_Apack = nullptr;
    __nv_bfloat16* p_B1 = nullptr;
    __nv_bfloat16* p_B2 = nullptr;
    cudaGetSymbolAddress((void**)&p_proj, g_proj);
    cudaGetSymbolAddress((void**)&p_Apack, g_Apack);
    cudaGetSymbolAddress((void**)&p_B1, g_B1);
    cudaGetSymbolAddress((void**)&p_B2, g_B2);

    cudaFuncSetAttribute(tgemm, cudaFuncAttributeMaxDynamicSharedMemorySize, GEMM_DYN_SMEM);
    cudaFuncSetAttribute(ssd_hmma, cudaFuncAttributeMaxDynamicSharedMemorySize, SSD_DYN_SMEM);

    // --- GEMM1 packs (split so tgemm is the 4th launch for ncu) ---
    pack_split<<<2048, 256>>>(x, p_Apack, SS, 0, SS, EMB, 0);
    pack_split<<<2048, 256>>>(w_in, p_B1, PROJD, 0, PROJPAD / 2, EMB, 1);
    pack_split<<<2048, 256>>>(w_in, p_B1, PROJD, PROJPAD / 2, PROJPAD, EMB, 1);
    // --- GEMM1: proj = X @ W_in^T ---
    tgemm<<<dim3(SS / 128, PROJPAD / 128), 256, GEMM_DYN_SMEM>>>(
        p_Apack, p_B1, p_proj, 3 * EMB, PROJD, PROJD);

    // --- elementwise / scan stages ---
    conv_silu_kernel<<<dim3(CONVD / 256, SS / 4), 256>>>(conv_w, conv_b);
    dtacum_kernel<<<dim3(NCH, NH), CSZ>>>(dt_bias, A_log);
    ssd_hmma<<<dim3(NCH, NH), 256, SSD_DYN_SMEM>>>(Dv);
    norm_pack_kernel<<<SS, 256>>>(norm_w);

    // --- GEMM2: out = normed @ W_out^T ---
    pack_split<<<2048, 256>>>(w_out, p_B2, EMB, 0, EMB, INTERD, 1);
    tgemm<<<dim3(SS / 128, EMB / 128), 256, GEMM_DYN_SMEM>>>(
        p_Apack, p_B2, out, 3 * INTERD, EMB, EMB);
}